// round 13
// baseline (speedup 1.0000x reference)
#include <cuda_runtime.h>
#include <cuda_fp16.h>

#define N_NODES 10000
#define D_IN    128
#define H1      128
#define H2      64
#define EMB     64
#define CAP     256      // fixed bucket capacity per destination node
#define NEG_SLOPE 0.2f
#define FULLMASK 0xffffffffu

// ---------------- scratch (device globals; no allocation allowed) -----------
__device__ __half g_h1h[N_NODES * H1];   // GEMM outputs stored fp16 (gather payload)
__device__ __half g_h2h[N_NODES * H2];
__device__ float  g_x1[N_NODES * H1];    // agg outputs stay fp32 (GEMM A operands)
__device__ float  g_x2[N_NODES * H2];
__device__ float  g_as[N_NODES];
__device__ float  g_ad[N_NODES];
__device__ int    g_cnt[N_NODES];        // zero-init at load; agg<64> resets -> launch-invariant
__device__ int    g_csr[N_NODES * CAP];  // bucket CSR: row i at i*CAP

// device-side scratch selector (host must NEVER pass device symbols directly)
__device__ __forceinline__ const float* abuf(int sel) {
    return (sel == 1) ? g_x1 : g_x2;
}

// ---------------- single-pass bucket CSR fill --------------------------------
__global__ void fill_bucket_kernel(const int* __restrict__ ei, int E) {
    int t = blockIdx.x * blockDim.x + threadIdx.x;
    int e0 = t * 2;
    if (e0 >= E) return;
    if (e0 + 2 <= E && ((E & 1) == 0)) {
        int2 s2 = *(const int2*)&ei[e0];
        int2 d2 = *(const int2*)&ei[E + e0];
        int p0 = ((unsigned)d2.x < N_NODES) ? atomicAdd(&g_cnt[d2.x], 1) : CAP;
        int p1 = ((unsigned)d2.y < N_NODES) ? atomicAdd(&g_cnt[d2.y], 1) : CAP;
        if (p0 < CAP && (unsigned)s2.x < N_NODES) g_csr[d2.x * CAP + p0] = s2.x;
        if (p1 < CAP && (unsigned)s2.y < N_NODES) g_csr[d2.y * CAP + p1] = s2.y;
    } else {
        for (int e = e0; e < E && e < e0 + 2; e++) {
            int s = ei[e];
            int d = ei[E + e];
            if ((unsigned)s < N_NODES && (unsigned)d < N_NODES) {
                int pos = atomicAdd(&g_cnt[d], 1);
                if (pos < CAP) g_csr[d * CAP + pos] = s;
            }
        }
    }
}

// ---------------- layer-1 GEMM: 16x128 tile (BK=16), fp16 out + direct dots --
// 256 threads: trow=tid>>5 (2 rows each, warp-uniform), tcol=tid&31 (4 cols).
__global__ void __launch_bounds__(256) gemm1_kernel(
        const float* __restrict__ A, const float* __restrict__ B,
        const float* __restrict__ a_src, const float* __restrict__ a_dst) {
    __shared__ __align__(16) float As[16][18];   // 16 k x 16 rows (+2 pad)
    __shared__ __align__(16) float Bs[16][128];
    const int tid  = threadIdx.x;
    const int trow = tid >> 5;                   // 0..7 (warp id)
    const int tcol = tid & 31;                   // 0..31
    const int m0 = blockIdx.x * 16;
    float acc[2][4] = {};

    for (int k0 = 0; k0 < D_IN; k0 += 16) {
        {   // As: 16 rows x 16 k = 256 (1 per thread)
            int r = tid >> 4, c = tid & 15;
            int gr = m0 + r;
            As[c][r] = (gr < N_NODES) ? A[gr * D_IN + k0 + c] : 0.f;
        }
#pragma unroll
        for (int t2 = tid; t2 < 2048; t2 += 256) {  // Bs: 16 k x 128 cols
            int r = t2 >> 7, c = t2 & 127;
            Bs[r][c] = B[(k0 + r) * H1 + c];
        }
        __syncthreads();
#pragma unroll
        for (int kk = 0; kk < 16; kk++) {
            float2 a2 = *(const float2*)&As[kk][trow * 2];
            float4 b4 = *(const float4*)&Bs[kk][tcol * 4];
            float bb[4] = {b4.x, b4.y, b4.z, b4.w};
            float aa[2] = {a2.x, a2.y};
#pragma unroll
            for (int i = 0; i < 2; i++)
#pragma unroll
                for (int j = 0; j < 4; j++)
                    acc[i][j] += aa[i] * bb[j];
        }
        __syncthreads();
    }

    // fp16 store: 2 rows x 4 cols = uint2 per row
#pragma unroll
    for (int i = 0; i < 2; i++) {
        int row = m0 + trow * 2 + i;
        if (row < N_NODES) {
            __half2 p0 = __floats2half2_rn(acc[i][0], acc[i][1]);
            __half2 p1 = __floats2half2_rn(acc[i][2], acc[i][3]);
            uint2 u;
            u.x = *reinterpret_cast<unsigned*>(&p0);
            u.y = *reinterpret_cast<unsigned*>(&p1);
            *(uint2*)&g_h1h[row * H1 + tcol * 4] = u;
        }
    }

    // attention dots: full-warp reduction (trow uniform per warp), direct store
    float asv[4], adv[4];
#pragma unroll
    for (int j = 0; j < 4; j++) {
        asv[j] = a_src[tcol * 4 + j];
        adv[j] = a_dst[tcol * 4 + j];
    }
#pragma unroll
    for (int i = 0; i < 2; i++) {
        float ds = 0.f, dd = 0.f;
#pragma unroll
        for (int j = 0; j < 4; j++) {
            ds += acc[i][j] * asv[j];
            dd += acc[i][j] * adv[j];
        }
#pragma unroll
        for (int off = 16; off; off >>= 1) {
            ds += __shfl_xor_sync(FULLMASK, ds, off);
            dd += __shfl_xor_sync(FULLMASK, dd, off);
        }
        int row = m0 + trow * 2 + i;
        if (tcol == 0 && row < N_NODES) {
            g_as[row] = ds;
            g_ad[row] = dd;
        }
    }
}

// ---------------- generic 16x64 GEMM (layer 2 + projection), BK=16 -----------
// 256 threads: trow=tid>>4 (1 row each), tcol=tid&15 (4 cols).
// A chosen by a_sel. out_mode: 0 -> fp16 g_h2h (+dots), 1 -> fp32 Cext (+bias).
__global__ void __launch_bounds__(256) gemm2_kernel(
        int a_sel, const float* __restrict__ B,
        const float* __restrict__ bias, float* __restrict__ Cext,
        int K, int out_mode,
        const float* __restrict__ a_src, const float* __restrict__ a_dst) {
    const float* A = abuf(a_sel);
    __shared__ __align__(16) float As[16][18];
    __shared__ __align__(16) float Bs[16][64];
    const int tid  = threadIdx.x;
    const int trow = tid >> 4;                // 0..15 (half-warp uniform)
    const int tcol = tid & 15;                // 0..15
    const int m0 = blockIdx.x * 16;
    float acc[4] = {};

    for (int k0 = 0; k0 < K; k0 += 16) {
        {   // As: 16 rows x 16 k = 256 (1 per thread)
            int r = tid >> 4, c = tid & 15;
            int gr = m0 + r;
            As[c][r] = (gr < N_NODES) ? A[gr * K + k0 + c] : 0.f;
        }
#pragma unroll
        for (int t2 = tid; t2 < 1024; t2 += 256) {  // Bs: 16 k x 64 cols
            int r = t2 >> 6, c = t2 & 63;
            Bs[r][c] = B[(k0 + r) * 64 + c];
        }
        __syncthreads();
#pragma unroll
        for (int kk = 0; kk < 16; kk++) {
            float a = As[kk][trow];
            float4 b4 = *(const float4*)&Bs[kk][tcol * 4];
            acc[0] += a * b4.x;
            acc[1] += a * b4.y;
            acc[2] += a * b4.z;
            acc[3] += a * b4.w;
        }
        __syncthreads();
    }

    int row = m0 + trow;
    if (out_mode == 0) {     // fp16 h2 + dots
        if (row < N_NODES) {
            __half2 p0 = __floats2half2_rn(acc[0], acc[1]);
            __half2 p1 = __floats2half2_rn(acc[2], acc[3]);
            uint2 u;
            u.x = *reinterpret_cast<unsigned*>(&p0);
            u.y = *reinterpret_cast<unsigned*>(&p1);
            *(uint2*)&g_h2h[row * H2 + tcol * 4] = u;
        }
        float ds = 0.f, dd = 0.f;
#pragma unroll
        for (int j = 0; j < 4; j++) {
            ds += acc[j] * a_src[tcol * 4 + j];
            dd += acc[j] * a_dst[tcol * 4 + j];
        }
#pragma unroll
        for (int off = 8; off; off >>= 1) {   // reduce within half-warp (same row)
            ds += __shfl_xor_sync(FULLMASK, ds, off);
            dd += __shfl_xor_sync(FULLMASK, dd, off);
        }
        if (tcol == 0 && row < N_NODES) {
            g_as[row] = ds;
            g_ad[row] = dd;
        }
    } else {                 // fp32 projection output + bias
        if (row < N_NODES) {
            float4 bv = *(const float4*)&bias[tcol * 4];
            float4 o;
            o.x = acc[0] + bv.x;
            o.y = acc[1] + bv.y;
            o.z = acc[2] + bv.z;
            o.w = acc[3] + bv.w;
            *(float4*)&Cext[row * EMB + tcol * 4] = o;
        }
    }
}

__device__ __forceinline__ float leaky(float x) {
    return x > 0.f ? x : NEG_SLOPE * x;
}

// ---------------- GAT aggregation: warp per destination node (R7 loop) -------
template <int H>
__global__ void __launch_bounds__(128) gat_agg_kernel(const float* __restrict__ bias) {
    const __half* hb = (H == 128) ? g_h1h : g_h2h;
    float* out       = (H == 128) ? g_x1 : g_x2;

    int i = (blockIdx.x * blockDim.x + threadIdx.x) >> 5;
    if (i >= N_NODES) return;
    int lane = threadIdx.x & 31;

    float adi = g_ad[i];
    int deg = g_cnt[i];
    if (lane == 0 && H == 64) g_cnt[i] = 0;   // last reader resets for next launch
    if (deg > CAP) deg = CAP;
    const int* row = &g_csr[i * CAP];

    constexpr int V = H / 32;
    float es = __expf(leaky(g_as[i] + adi));
    float zl = (lane == 0) ? es : 0.f;
    float acc[V];
    if (V == 4) {
        uint2 u = *(const uint2*)&hb[i * H + lane * 4];
        float2 f0 = __half22float2(*reinterpret_cast<const __half2*>(&u.x));
        float2 f1 = __half22float2(*reinterpret_cast<const __half2*>(&u.y));
        acc[0] = es * f0.x; acc[1] = es * f0.y;
        acc[2] = es * f1.x; acc[3] = es * f1.y;
    } else {
        float2 f = __half22float2(*(const __half2*)&hb[i * H + lane * 2]);
        acc[0] = es * f.x; acc[1] = es * f.y;
    }

    for (int base = 0; base < deg; base += 32) {
        int rem = deg - base;
        if (rem > 32) rem = 32;

        int   idx = 0;
        float e   = 0.f;
        if (lane < rem) {
            idx = __ldg(&row[base + lane]);
            e   = __expf(leaky(__ldg(&g_as[idx]) + adi));
        }
        zl += e;

        int k = 0;
        for (; k + 4 <= rem; k += 4) {
            int   s0 = __shfl_sync(FULLMASK, idx, k);
            int   s1 = __shfl_sync(FULLMASK, idx, k + 1);
            int   s2 = __shfl_sync(FULLMASK, idx, k + 2);
            int   s3 = __shfl_sync(FULLMASK, idx, k + 3);
            float w0 = __shfl_sync(FULLMASK, e, k);
            float w1 = __shfl_sync(FULLMASK, e, k + 1);
            float w2 = __shfl_sync(FULLMASK, e, k + 2);
            float w3 = __shfl_sync(FULLMASK, e, k + 3);
            if (V == 4) {
                uint2 u0 = *(const uint2*)&hb[s0 * H + lane * 4];
                uint2 u1 = *(const uint2*)&hb[s1 * H + lane * 4];
                uint2 u2 = *(const uint2*)&hb[s2 * H + lane * 4];
                uint2 u3 = *(const uint2*)&hb[s3 * H + lane * 4];
                float2 a0 = __half22float2(*reinterpret_cast<const __half2*>(&u0.x));
                float2 b0 = __half22float2(*reinterpret_cast<const __half2*>(&u0.y));
                float2 a1 = __half22float2(*reinterpret_cast<const __half2*>(&u1.x));
                float2 b1 = __half22float2(*reinterpret_cast<const __half2*>(&u1.y));
                float2 a2 = __half22float2(*reinterpret_cast<const __half2*>(&u2.x));
                float2 b2 = __half22float2(*reinterpret_cast<const __half2*>(&u2.y));
                float2 a3 = __half22float2(*reinterpret_cast<const __half2*>(&u3.x));
                float2 b3 = __half22float2(*reinterpret_cast<const __half2*>(&u3.y));
                acc[0] += w0 * a0.x + w1 * a1.x + w2 * a2.x + w3 * a3.x;
                acc[1] += w0 * a0.y + w1 * a1.y + w2 * a2.y + w3 * a3.y;
                acc[2] += w0 * b0.x + w1 * b1.x + w2 * b2.x + w3 * b3.x;
                acc[3] += w0 * b0.y + w1 * b1.y + w2 * b2.y + w3 * b3.y;
            } else {
                float2 f0 = __half22float2(*(const __half2*)&hb[s0 * H + lane * 2]);
                float2 f1 = __half22float2(*(const __half2*)&hb[s1 * H + lane * 2]);
                float2 f2 = __half22float2(*(const __half2*)&hb[s2 * H + lane * 2]);
                float2 f3 = __half22float2(*(const __half2*)&hb[s3 * H + lane * 2]);
                acc[0] += w0 * f0.x + w1 * f1.x + w2 * f2.x + w3 * f3.x;
                acc[1] += w0 * f0.y + w1 * f1.y + w2 * f2.y + w3 * f3.y;
            }
        }
        for (; k < rem; ++k) {
            int   s0 = __shfl_sync(FULLMASK, idx, k);
            float w0 = __shfl_sync(FULLMASK, e, k);
            if (V == 4) {
                uint2 u0 = *(const uint2*)&hb[s0 * H + lane * 4];
                float2 a0 = __half22float2(*reinterpret_cast<const __half2*>(&u0.x));
                float2 b0 = __half22float2(*reinterpret_cast<const __half2*>(&u0.y));
                acc[0] += w0 * a0.x; acc[1] += w0 * a0.y;
                acc[2] += w0 * b0.x; acc[3] += w0 * b0.y;
            } else {
                float2 f0 = __half22float2(*(const __half2*)&hb[s0 * H + lane * 2]);
                acc[0] += w0 * f0.x; acc[1] += w0 * f0.y;
            }
        }
    }

#pragma unroll
    for (int off = 16; off; off >>= 1) zl += __shfl_xor_sync(FULLMASK, zl, off);

    float inv = 1.f / zl;
#pragma unroll
    for (int v = 0; v < V; v++) {
        float r = acc[v] * inv + bias[lane * V + v];
        out[i * H + lane * V + v] = r > 0.f ? r : 0.f;
    }
}

// ---------------- launch -----------------------------------------------------
extern "C" void kernel_launch(void* const* d_in, const int* in_sizes, int n_in,
                              void* d_out, int out_size) {
    const float* x    = (const float*)d_in[0];
    const int*   ei   = (const int*)d_in[1];       // int32 edge_index [2, E]
    const float* W1   = (const float*)d_in[2];
    const float* a_s1 = (const float*)d_in[3];
    const float* a_d1 = (const float*)d_in[4];
    const float* b1   = (const float*)d_in[5];
    const float* W2   = (const float*)d_in[6];
    const float* a_s2 = (const float*)d_in[7];
    const float* a_d2 = (const float*)d_in[8];
    const float* b2   = (const float*)d_in[9];
    const float* Wp   = (const float*)d_in[10];
    const float* bp   = (const float*)d_in[11];
    const int E = in_sizes[1] / 2;

    const int TB = 256;
    const int AB = 128;
    const int aggBlocks  = (N_NODES * 32 + AB - 1) / AB;
    const int gemmBlocks = (N_NODES + 15) / 16;   // 625

    // CSR fill (g_cnt zero: static init on first launch, agg<64> resets after)
    fill_bucket_kernel<<<(E + TB * 2 - 1) / (TB * 2), TB>>>(ei, E);

    // layer 1: h1(fp16) = x @ W1 (+direct dots) ; x1 = agg(h1)
    gemm1_kernel<<<gemmBlocks, TB>>>(x, W1, a_s1, a_d1);
    gat_agg_kernel<H1><<<aggBlocks, AB>>>(b1);

    // layer 2: h2(fp16) = x1 @ W2 (+direct dots) ; x2 = agg(h2) [resets g_cnt]
    gemm2_kernel<<<gemmBlocks, TB>>>(1, W2, nullptr, nullptr, H1, 0, a_s2, a_d2);
    gat_agg_kernel<H2><<<aggBlocks, AB>>>(b2);

    // projection: out = x2 @ Wp + bp (fp32)
    gemm2_kernel<<<gemmBlocks, TB>>>(2, Wp, bp, (float*)d_out, H2, 1,
                                     nullptr, nullptr);
}

// round 14
// speedup vs baseline: 1.4395x; 1.4395x over previous
#include <cuda_runtime.h>
#include <cuda_fp16.h>

#define N_NODES 10000
#define D_IN    128
#define H1      128
#define H2      64
#define EMB     64
#define CAP     256      // fixed bucket capacity per destination node
#define NEG_SLOPE 0.2f
#define FULLMASK 0xffffffffu

// ---------------- scratch (device globals; no allocation allowed) -----------
__device__ __half g_h1h[N_NODES * H1];   // GEMM outputs stored fp16 (gather payload)
__device__ __half g_h2h[N_NODES * H2];
__device__ float  g_x1[N_NODES * H1];    // agg outputs stay fp32 (GEMM A operands)
__device__ float  g_x2[N_NODES * H2];
__device__ float  g_as[N_NODES];
__device__ float  g_ad[N_NODES];
__device__ int    g_cnt[N_NODES];        // zero-init at load; agg<64> resets -> launch-invariant
__device__ int    g_csr[N_NODES * CAP];  // bucket CSR: row i at i*CAP

// device-side scratch selector (host must NEVER pass device symbols directly)
__device__ __forceinline__ const float* abuf(int sel) {
    return (sel == 1) ? g_x1 : g_x2;
}

// ---------------- single-pass bucket CSR fill --------------------------------
__global__ void fill_bucket_kernel(const int* __restrict__ ei, int E) {
    int t = blockIdx.x * blockDim.x + threadIdx.x;
    int e0 = t * 2;
    if (e0 >= E) return;
    if (e0 + 2 <= E && ((E & 1) == 0)) {
        int2 s2 = *(const int2*)&ei[e0];
        int2 d2 = *(const int2*)&ei[E + e0];
        int p0 = ((unsigned)d2.x < N_NODES) ? atomicAdd(&g_cnt[d2.x], 1) : CAP;
        int p1 = ((unsigned)d2.y < N_NODES) ? atomicAdd(&g_cnt[d2.y], 1) : CAP;
        if (p0 < CAP && (unsigned)s2.x < N_NODES) g_csr[d2.x * CAP + p0] = s2.x;
        if (p1 < CAP && (unsigned)s2.y < N_NODES) g_csr[d2.y * CAP + p1] = s2.y;
    } else {
        for (int e = e0; e < E && e < e0 + 2; e++) {
            int s = ei[e];
            int d = ei[E + e];
            if ((unsigned)s < N_NODES && (unsigned)d < N_NODES) {
                int pos = atomicAdd(&g_cnt[d], 1);
                if (pos < CAP) g_csr[d * CAP + pos] = s;
            }
        }
    }
}

// ---------------- layer-1 GEMM: 32x128 tile (BK=16), double-buffered ---------
// 256 threads: trow=tid>>4 (2 rows each), tcol=tid&15 (8 cols each).
__global__ void __launch_bounds__(256) gemm1_kernel(
        const float* __restrict__ A, const float* __restrict__ B,
        const float* __restrict__ a_src, const float* __restrict__ a_dst) {
    __shared__ __align__(16) float As[16][34];   // +2 pad
    __shared__ __align__(16) float Bs[16][128];
    const int tid  = threadIdx.x;
    const int trow = tid >> 4;                   // 0..15
    const int tcol = tid & 15;                   // 0..15
    const int m0 = blockIdx.x * 32;
    float acc[2][8] = {};

    float aR[2], bR[8];
    // preload k0 = 0
#pragma unroll
    for (int u = 0; u < 2; u++) {
        int idx = tid + u * 256, r = idx >> 4, c = idx & 15, gr = m0 + r;
        aR[u] = (gr < N_NODES) ? A[gr * D_IN + c] : 0.f;
    }
#pragma unroll
    for (int u = 0; u < 8; u++) {
        int idx = tid + u * 256, r = idx >> 7, c = idx & 127;
        bR[u] = B[r * H1 + c];
    }

    for (int k0 = 0; k0 < D_IN; k0 += 16) {
#pragma unroll
        for (int u = 0; u < 2; u++) {
            int idx = tid + u * 256, r = idx >> 4, c = idx & 15;
            As[c][r] = aR[u];
        }
#pragma unroll
        for (int u = 0; u < 8; u++) {
            int idx = tid + u * 256, r = idx >> 7, c = idx & 127;
            Bs[r][c] = bR[u];
        }
        __syncthreads();

        int k1 = k0 + 16;
        if (k1 < D_IN) {   // prefetch next tile while computing current
#pragma unroll
            for (int u = 0; u < 2; u++) {
                int idx = tid + u * 256, r = idx >> 4, c = idx & 15, gr = m0 + r;
                aR[u] = (gr < N_NODES) ? A[gr * D_IN + k1 + c] : 0.f;
            }
#pragma unroll
            for (int u = 0; u < 8; u++) {
                int idx = tid + u * 256, r = idx >> 7, c = idx & 127;
                bR[u] = B[(k1 + r) * H1 + c];
            }
        }

#pragma unroll
        for (int kk = 0; kk < 16; kk++) {
            float2 a2 = *(const float2*)&As[kk][trow * 2];
            float4 b0 = *(const float4*)&Bs[kk][tcol * 8];
            float4 b1 = *(const float4*)&Bs[kk][tcol * 8 + 4];
            float bb[8] = {b0.x, b0.y, b0.z, b0.w, b1.x, b1.y, b1.z, b1.w};
            float aa[2] = {a2.x, a2.y};
#pragma unroll
            for (int i = 0; i < 2; i++)
#pragma unroll
                for (int j = 0; j < 8; j++)
                    acc[i][j] += aa[i] * bb[j];
        }
        __syncthreads();
    }

    // fp16 store: 2 rows x 8 cols = one uint4 per row
#pragma unroll
    for (int i = 0; i < 2; i++) {
        int row = m0 + trow * 2 + i;
        if (row < N_NODES) {
            __half2 p0 = __floats2half2_rn(acc[i][0], acc[i][1]);
            __half2 p1 = __floats2half2_rn(acc[i][2], acc[i][3]);
            __half2 p2 = __floats2half2_rn(acc[i][4], acc[i][5]);
            __half2 p3 = __floats2half2_rn(acc[i][6], acc[i][7]);
            uint4 u;
            u.x = *reinterpret_cast<unsigned*>(&p0);
            u.y = *reinterpret_cast<unsigned*>(&p1);
            u.z = *reinterpret_cast<unsigned*>(&p2);
            u.w = *reinterpret_cast<unsigned*>(&p3);
            *(uint4*)&g_h1h[row * H1 + tcol * 8] = u;
        }
    }

    // attention dots: reduce over the 16-lane tcol group, direct store
    float asv[8], adv[8];
#pragma unroll
    for (int j = 0; j < 8; j++) {
        asv[j] = a_src[tcol * 8 + j];
        adv[j] = a_dst[tcol * 8 + j];
    }
#pragma unroll
    for (int i = 0; i < 2; i++) {
        float ds = 0.f, dd = 0.f;
#pragma unroll
        for (int j = 0; j < 8; j++) {
            ds += acc[i][j] * asv[j];
            dd += acc[i][j] * adv[j];
        }
#pragma unroll
        for (int off = 8; off; off >>= 1) {
            ds += __shfl_xor_sync(FULLMASK, ds, off);
            dd += __shfl_xor_sync(FULLMASK, dd, off);
        }
        int row = m0 + trow * 2 + i;
        if (tcol == 0 && row < N_NODES) {
            g_as[row] = ds;
            g_ad[row] = dd;
        }
    }
}

// ---------------- generic 32x64 GEMM (layer 2 + projection), double-buffered -
// A chosen by a_sel (device-side). out_mode: 0 -> fp16 g_h2h (+dots),
// 1 -> fp32 Cext (+bias).
__global__ void __launch_bounds__(256) gemm2_kernel(
        int a_sel, const float* __restrict__ B,
        const float* __restrict__ bias, float* __restrict__ Cext,
        int K, int out_mode,
        const float* __restrict__ a_src, const float* __restrict__ a_dst) {
    const float* A = abuf(a_sel);
    __shared__ __align__(16) float As[16][34];
    __shared__ __align__(16) float Bs[16][64];
    const int tid  = threadIdx.x;
    const int trow = tid >> 4;
    const int tcol = tid & 15;
    const int m0 = blockIdx.x * 32;
    float acc[2][4] = {};

    float aR[2], bR[4];
#pragma unroll
    for (int u = 0; u < 2; u++) {
        int idx = tid + u * 256, r = idx >> 4, c = idx & 15, gr = m0 + r;
        aR[u] = (gr < N_NODES) ? A[gr * K + c] : 0.f;
    }
#pragma unroll
    for (int u = 0; u < 4; u++) {
        int idx = tid + u * 256, r = idx >> 6, c = idx & 63;
        bR[u] = B[r * 64 + c];
    }

    for (int k0 = 0; k0 < K; k0 += 16) {
#pragma unroll
        for (int u = 0; u < 2; u++) {
            int idx = tid + u * 256, r = idx >> 4, c = idx & 15;
            As[c][r] = aR[u];
        }
#pragma unroll
        for (int u = 0; u < 4; u++) {
            int idx = tid + u * 256, r = idx >> 6, c = idx & 63;
            Bs[r][c] = bR[u];
        }
        __syncthreads();

        int k1 = k0 + 16;
        if (k1 < K) {   // prefetch next tile
#pragma unroll
            for (int u = 0; u < 2; u++) {
                int idx = tid + u * 256, r = idx >> 4, c = idx & 15, gr = m0 + r;
                aR[u] = (gr < N_NODES) ? A[gr * K + k1 + c] : 0.f;
            }
#pragma unroll
            for (int u = 0; u < 4; u++) {
                int idx = tid + u * 256, r = idx >> 6, c = idx & 63;
                bR[u] = B[(k1 + r) * 64 + c];
            }
        }

#pragma unroll
        for (int kk = 0; kk < 16; kk++) {
            float2 a2 = *(const float2*)&As[kk][trow * 2];
            float4 b4 = *(const float4*)&Bs[kk][tcol * 4];
            float bb[4] = {b4.x, b4.y, b4.z, b4.w};
            float aa[2] = {a2.x, a2.y};
#pragma unroll
            for (int i = 0; i < 2; i++)
#pragma unroll
                for (int j = 0; j < 4; j++)
                    acc[i][j] += aa[i] * bb[j];
        }
        __syncthreads();
    }

    if (out_mode == 0) {     // fp16 h2 + dots
#pragma unroll
        for (int i = 0; i < 2; i++) {
            int row = m0 + trow * 2 + i;
            if (row < N_NODES) {
                __half2 p0 = __floats2half2_rn(acc[i][0], acc[i][1]);
                __half2 p1 = __floats2half2_rn(acc[i][2], acc[i][3]);
                uint2 u;
                u.x = *reinterpret_cast<unsigned*>(&p0);
                u.y = *reinterpret_cast<unsigned*>(&p1);
                *(uint2*)&g_h2h[row * H2 + tcol * 4] = u;
            }
        }
        float asv[4], adv[4];
#pragma unroll
        for (int j = 0; j < 4; j++) {
            asv[j] = a_src[tcol * 4 + j];
            adv[j] = a_dst[tcol * 4 + j];
        }
#pragma unroll
        for (int i = 0; i < 2; i++) {
            float ds = 0.f, dd = 0.f;
#pragma unroll
            for (int j = 0; j < 4; j++) {
                ds += acc[i][j] * asv[j];
                dd += acc[i][j] * adv[j];
            }
#pragma unroll
            for (int off = 8; off; off >>= 1) {
                ds += __shfl_xor_sync(FULLMASK, ds, off);
                dd += __shfl_xor_sync(FULLMASK, dd, off);
            }
            int row = m0 + trow * 2 + i;
            if (tcol == 0 && row < N_NODES) {
                g_as[row] = ds;
                g_ad[row] = dd;
            }
        }
    } else {                 // fp32 projection output + bias
        float4 bv = *(const float4*)&bias[tcol * 4];
#pragma unroll
        for (int i = 0; i < 2; i++) {
            int row = m0 + trow * 2 + i;
            if (row < N_NODES) {
                float4 o;
                o.x = acc[i][0] + bv.x;
                o.y = acc[i][1] + bv.y;
                o.z = acc[i][2] + bv.z;
                o.w = acc[i][3] + bv.w;
                *(float4*)&Cext[row * EMB + tcol * 4] = o;
            }
        }
    }
}

__device__ __forceinline__ float leaky(float x) {
    return x > 0.f ? x : NEG_SLOPE * x;
}

// ---------------- GAT aggregation: warp per destination node (R7 loop) -------
template <int H>
__global__ void __launch_bounds__(128) gat_agg_kernel(const float* __restrict__ bias) {
    const __half* hb = (H == 128) ? g_h1h : g_h2h;
    float* out       = (H == 128) ? g_x1 : g_x2;

    int i = (blockIdx.x * blockDim.x + threadIdx.x) >> 5;
    if (i >= N_NODES) return;
    int lane = threadIdx.x & 31;

    float adi = g_ad[i];
    int deg = g_cnt[i];
    if (lane == 0 && H == 64) g_cnt[i] = 0;   // last reader resets for next launch
    if (deg > CAP) deg = CAP;
    const int* row = &g_csr[i * CAP];

    constexpr int V = H / 32;
    float es = __expf(leaky(g_as[i] + adi));
    float zl = (lane == 0) ? es : 0.f;
    float acc[V];
    if (V == 4) {
        uint2 u = *(const uint2*)&hb[i * H + lane * 4];
        float2 f0 = __half22float2(*reinterpret_cast<const __half2*>(&u.x));
        float2 f1 = __half22float2(*reinterpret_cast<const __half2*>(&u.y));
        acc[0] = es * f0.x; acc[1] = es * f0.y;
        acc[2] = es * f1.x; acc[3] = es * f1.y;
    } else {
        float2 f = __half22float2(*(const __half2*)&hb[i * H + lane * 2]);
        acc[0] = es * f.x; acc[1] = es * f.y;
    }

    for (int base = 0; base < deg; base += 32) {
        int rem = deg - base;
        if (rem > 32) rem = 32;

        int   idx = 0;
        float e   = 0.f;
        if (lane < rem) {
            idx = __ldg(&row[base + lane]);
            e   = __expf(leaky(__ldg(&g_as[idx]) + adi));
        }
        zl += e;

        int k = 0;
        for (; k + 4 <= rem; k += 4) {
            int   s0 = __shfl_sync(FULLMASK, idx, k);
            int   s1 = __shfl_sync(FULLMASK, idx, k + 1);
            int   s2 = __shfl_sync(FULLMASK, idx, k + 2);
            int   s3 = __shfl_sync(FULLMASK, idx, k + 3);
            float w0 = __shfl_sync(FULLMASK, e, k);
            float w1 = __shfl_sync(FULLMASK, e, k + 1);
            float w2 = __shfl_sync(FULLMASK, e, k + 2);
            float w3 = __shfl_sync(FULLMASK, e, k + 3);
            if (V == 4) {
                uint2 u0 = *(const uint2*)&hb[s0 * H + lane * 4];
                uint2 u1 = *(const uint2*)&hb[s1 * H + lane * 4];
                uint2 u2 = *(const uint2*)&hb[s2 * H + lane * 4];
                uint2 u3 = *(const uint2*)&hb[s3 * H + lane * 4];
                float2 a0 = __half22float2(*reinterpret_cast<const __half2*>(&u0.x));
                float2 b0 = __half22float2(*reinterpret_cast<const __half2*>(&u0.y));
                float2 a1 = __half22float2(*reinterpret_cast<const __half2*>(&u1.x));
                float2 b1 = __half22float2(*reinterpret_cast<const __half2*>(&u1.y));
                float2 a2 = __half22float2(*reinterpret_cast<const __half2*>(&u2.x));
                float2 b2 = __half22float2(*reinterpret_cast<const __half2*>(&u2.y));
                float2 a3 = __half22float2(*reinterpret_cast<const __half2*>(&u3.x));
                float2 b3 = __half22float2(*reinterpret_cast<const __half2*>(&u3.y));
                acc[0] += w0 * a0.x + w1 * a1.x + w2 * a2.x + w3 * a3.x;
                acc[1] += w0 * a0.y + w1 * a1.y + w2 * a2.y + w3 * a3.y;
                acc[2] += w0 * b0.x + w1 * b1.x + w2 * b2.x + w3 * b3.x;
                acc[3] += w0 * b0.y + w1 * b1.y + w2 * b2.y + w3 * b3.y;
            } else {
                float2 f0 = __half22float2(*(const __half2*)&hb[s0 * H + lane * 2]);
                float2 f1 = __half22float2(*(const __half2*)&hb[s1 * H + lane * 2]);
                float2 f2 = __half22float2(*(const __half2*)&hb[s2 * H + lane * 2]);
                float2 f3 = __half22float2(*(const __half2*)&hb[s3 * H + lane * 2]);
                acc[0] += w0 * f0.x + w1 * f1.x + w2 * f2.x + w3 * f3.x;
                acc[1] += w0 * f0.y + w1 * f1.y + w2 * f2.y + w3 * f3.y;
            }
        }
        for (; k < rem; ++k) {
            int   s0 = __shfl_sync(FULLMASK, idx, k);
            float w0 = __shfl_sync(FULLMASK, e, k);
            if (V == 4) {
                uint2 u0 = *(const uint2*)&hb[s0 * H + lane * 4];
                float2 a0 = __half22float2(*reinterpret_cast<const __half2*>(&u0.x));
                float2 b0 = __half22float2(*reinterpret_cast<const __half2*>(&u0.y));
                acc[0] += w0 * a0.x; acc[1] += w0 * a0.y;
                acc[2] += w0 * b0.x; acc[3] += w0 * b0.y;
            } else {
                float2 f0 = __half22float2(*(const __half2*)&hb[s0 * H + lane * 2]);
                acc[0] += w0 * f0.x; acc[1] += w0 * f0.y;
            }
        }
    }

#pragma unroll
    for (int off = 16; off; off >>= 1) zl += __shfl_xor_sync(FULLMASK, zl, off);

    float inv = 1.f / zl;
#pragma unroll
    for (int v = 0; v < V; v++) {
        float r = acc[v] * inv + bias[lane * V + v];
        out[i * H + lane * V + v] = r > 0.f ? r : 0.f;
    }
}

// ---------------- launch -----------------------------------------------------
extern "C" void kernel_launch(void* const* d_in, const int* in_sizes, int n_in,
                              void* d_out, int out_size) {
    const float* x    = (const float*)d_in[0];
    const int*   ei   = (const int*)d_in[1];       // int32 edge_index [2, E]
    const float* W1   = (const float*)d_in[2];
    const float* a_s1 = (const float*)d_in[3];
    const float* a_d1 = (const float*)d_in[4];
    const float* b1   = (const float*)d_in[5];
    const float* W2   = (const float*)d_in[6];
    const float* a_s2 = (const float*)d_in[7];
    const float* a_d2 = (const float*)d_in[8];
    const float* b2   = (const float*)d_in[9];
    const float* Wp   = (const float*)d_in[10];
    const float* bp   = (const float*)d_in[11];
    const int E = in_sizes[1] / 2;

    const int TB = 256;
    const int AB = 128;
    const int aggBlocks  = (N_NODES * 32 + AB - 1) / AB;
    const int gemmBlocks = (N_NODES + 31) / 32;   // 313

    // CSR fill (g_cnt zero: static init on first launch, agg<64> resets after)
    fill_bucket_kernel<<<(E + TB * 2 - 1) / (TB * 2), TB>>>(ei, E);

    // layer 1: h1(fp16) = x @ W1 (+direct dots) ; x1 = agg(h1)
    gemm1_kernel<<<gemmBlocks, TB>>>(x, W1, a_s1, a_d1);
    gat_agg_kernel<H1><<<aggBlocks, AB>>>(b1);

    // layer 2: h2(fp16) = x1 @ W2 (+direct dots) ; x2 = agg(h2) [resets g_cnt]
    gemm2_kernel<<<gemmBlocks, TB>>>(1, W2, nullptr, nullptr, H1, 0, a_s2, a_d2);
    gat_agg_kernel<H2><<<aggBlocks, AB>>>(b2);

    // projection: out = x2 @ Wp + bp (fp32)
    gemm2_kernel<<<gemmBlocks, TB>>>(2, Wp, bp, (float*)d_out, H2, 1,
                                     nullptr, nullptr);
}

// round 15
// speedup vs baseline: 1.6145x; 1.1216x over previous
#include <cuda_runtime.h>
#include <cuda_fp16.h>

#define N_NODES 10000
#define D_IN    128
#define H1      128
#define H2      64
#define EMB     64
#define CAP     256      // fixed bucket capacity per destination node
#define NEG_SLOPE 0.2f
#define FULLMASK 0xffffffffu

// ---------------- scratch (device globals; no allocation allowed) -----------
__device__ __half g_h1h[N_NODES * H1];   // GEMM outputs stored fp16 (gather payload)
__device__ __half g_h2h[N_NODES * H2];
__device__ float  g_x1[N_NODES * H1];    // agg output (GEMM A operand)
__device__ float  g_as[N_NODES];
__device__ float  g_ad[N_NODES];
__device__ int    g_cnt[N_NODES];        // zero-init at load; agg<64> resets -> launch-invariant
__device__ int    g_csr[N_NODES * CAP];  // bucket CSR: row i at i*CAP

__device__ __forceinline__ float leaky(float x) {
    return x > 0.f ? x : NEG_SLOPE * x;
}

// ---------------- fused: gemm1 (blocks [0, gemmBlocks)) + CSR fill (rest) ----
// gemm1: h1(fp16) = x @ W1, 32x128 tile, BK=16, double-buffered, direct dots.
// fill : bucket CSR build, 2 edges/thread.
__global__ void __launch_bounds__(256) fused_fill_gemm1_kernel(
        const int* __restrict__ ei, int E,
        const float* __restrict__ A, const float* __restrict__ B,
        const float* __restrict__ a_src, const float* __restrict__ a_dst,
        int gemmBlocks) {
    const int tid = threadIdx.x;

    if (blockIdx.x >= gemmBlocks) {
        // ---------------- CSR fill path ----------------
        int t = (blockIdx.x - gemmBlocks) * blockDim.x + tid;
        int e0 = t * 2;
        if (e0 >= E) return;
        if (e0 + 2 <= E && ((E & 1) == 0)) {
            int2 s2 = *(const int2*)&ei[e0];
            int2 d2 = *(const int2*)&ei[E + e0];
            int p0 = ((unsigned)d2.x < N_NODES) ? atomicAdd(&g_cnt[d2.x], 1) : CAP;
            int p1 = ((unsigned)d2.y < N_NODES) ? atomicAdd(&g_cnt[d2.y], 1) : CAP;
            if (p0 < CAP && (unsigned)s2.x < N_NODES) g_csr[d2.x * CAP + p0] = s2.x;
            if (p1 < CAP && (unsigned)s2.y < N_NODES) g_csr[d2.y * CAP + p1] = s2.y;
        } else {
            for (int e = e0; e < E && e < e0 + 2; e++) {
                int s = ei[e];
                int d = ei[E + e];
                if ((unsigned)s < N_NODES && (unsigned)d < N_NODES) {
                    int pos = atomicAdd(&g_cnt[d], 1);
                    if (pos < CAP) g_csr[d * CAP + pos] = s;
                }
            }
        }
        return;
    }

    // ---------------- gemm1 path ----------------
    __shared__ __align__(16) float As[16][34];
    __shared__ __align__(16) float Bs[16][128];
    const int trow = tid >> 4;                   // 0..15
    const int tcol = tid & 15;                   // 0..15
    const int m0 = blockIdx.x * 32;
    float acc[2][8] = {};

    float aR[2], bR[8];
#pragma unroll
    for (int u = 0; u < 2; u++) {
        int idx = tid + u * 256, r = idx >> 4, c = idx & 15, gr = m0 + r;
        aR[u] = (gr < N_NODES) ? A[gr * D_IN + c] : 0.f;
    }
#pragma unroll
    for (int u = 0; u < 8; u++) {
        int idx = tid + u * 256, r = idx >> 7, c = idx & 127;
        bR[u] = B[r * H1 + c];
    }

    for (int k0 = 0; k0 < D_IN; k0 += 16) {
#pragma unroll
        for (int u = 0; u < 2; u++) {
            int idx = tid + u * 256, r = idx >> 4, c = idx & 15;
            As[c][r] = aR[u];
        }
#pragma unroll
        for (int u = 0; u < 8; u++) {
            int idx = tid + u * 256, r = idx >> 7, c = idx & 127;
            Bs[r][c] = bR[u];
        }
        __syncthreads();

        int k1 = k0 + 16;
        if (k1 < D_IN) {
#pragma unroll
            for (int u = 0; u < 2; u++) {
                int idx = tid + u * 256, r = idx >> 4, c = idx & 15, gr = m0 + r;
                aR[u] = (gr < N_NODES) ? A[gr * D_IN + k1 + c] : 0.f;
            }
#pragma unroll
            for (int u = 0; u < 8; u++) {
                int idx = tid + u * 256, r = idx >> 7, c = idx & 127;
                bR[u] = B[(k1 + r) * H1 + c];
            }
        }

#pragma unroll
        for (int kk = 0; kk < 16; kk++) {
            float2 a2 = *(const float2*)&As[kk][trow * 2];
            float4 b0 = *(const float4*)&Bs[kk][tcol * 8];
            float4 b1 = *(const float4*)&Bs[kk][tcol * 8 + 4];
            float bb[8] = {b0.x, b0.y, b0.z, b0.w, b1.x, b1.y, b1.z, b1.w};
            float aa[2] = {a2.x, a2.y};
#pragma unroll
            for (int i = 0; i < 2; i++)
#pragma unroll
                for (int j = 0; j < 8; j++)
                    acc[i][j] += aa[i] * bb[j];
        }
        __syncthreads();
    }

#pragma unroll
    for (int i = 0; i < 2; i++) {
        int row = m0 + trow * 2 + i;
        if (row < N_NODES) {
            __half2 p0 = __floats2half2_rn(acc[i][0], acc[i][1]);
            __half2 p1 = __floats2half2_rn(acc[i][2], acc[i][3]);
            __half2 p2 = __floats2half2_rn(acc[i][4], acc[i][5]);
            __half2 p3 = __floats2half2_rn(acc[i][6], acc[i][7]);
            uint4 u;
            u.x = *reinterpret_cast<unsigned*>(&p0);
            u.y = *reinterpret_cast<unsigned*>(&p1);
            u.z = *reinterpret_cast<unsigned*>(&p2);
            u.w = *reinterpret_cast<unsigned*>(&p3);
            *(uint4*)&g_h1h[row * H1 + tcol * 8] = u;
        }
    }

    float asv[8], adv[8];
#pragma unroll
    for (int j = 0; j < 8; j++) {
        asv[j] = a_src[tcol * 8 + j];
        adv[j] = a_dst[tcol * 8 + j];
    }
#pragma unroll
    for (int i = 0; i < 2; i++) {
        float ds = 0.f, dd = 0.f;
#pragma unroll
        for (int j = 0; j < 8; j++) {
            ds += acc[i][j] * asv[j];
            dd += acc[i][j] * adv[j];
        }
#pragma unroll
        for (int off = 8; off; off >>= 1) {
            ds += __shfl_xor_sync(FULLMASK, ds, off);
            dd += __shfl_xor_sync(FULLMASK, dd, off);
        }
        int row = m0 + trow * 2 + i;
        if (tcol == 0 && row < N_NODES) {
            g_as[row] = ds;
            g_ad[row] = dd;
        }
    }
}

// ---------------- gemm2: h2(fp16) = x1 @ W2, 32x64 tile, double-buffered -----
__global__ void __launch_bounds__(256) gemm2_kernel(
        const float* __restrict__ B,
        const float* __restrict__ a_src, const float* __restrict__ a_dst) {
    const float* A = g_x1;
    __shared__ __align__(16) float As[16][34];
    __shared__ __align__(16) float Bs[16][64];
    const int tid  = threadIdx.x;
    const int trow = tid >> 4;
    const int tcol = tid & 15;
    const int m0 = blockIdx.x * 32;
    float acc[2][4] = {};

    float aR[2], bR[4];
#pragma unroll
    for (int u = 0; u < 2; u++) {
        int idx = tid + u * 256, r = idx >> 4, c = idx & 15, gr = m0 + r;
        aR[u] = (gr < N_NODES) ? A[gr * H1 + c] : 0.f;
    }
#pragma unroll
    for (int u = 0; u < 4; u++) {
        int idx = tid + u * 256, r = idx >> 6, c = idx & 63;
        bR[u] = B[r * 64 + c];
    }

    for (int k0 = 0; k0 < H1; k0 += 16) {
#pragma unroll
        for (int u = 0; u < 2; u++) {
            int idx = tid + u * 256, r = idx >> 4, c = idx & 15;
            As[c][r] = aR[u];
        }
#pragma unroll
        for (int u = 0; u < 4; u++) {
            int idx = tid + u * 256, r = idx >> 6, c = idx & 63;
            Bs[r][c] = bR[u];
        }
        __syncthreads();

        int k1 = k0 + 16;
        if (k1 < H1) {
#pragma unroll
            for (int u = 0; u < 2; u++) {
                int idx = tid + u * 256, r = idx >> 4, c = idx & 15, gr = m0 + r;
                aR[u] = (gr < N_NODES) ? A[gr * H1 + k1 + c] : 0.f;
            }
#pragma unroll
            for (int u = 0; u < 4; u++) {
                int idx = tid + u * 256, r = idx >> 6, c = idx & 63;
                bR[u] = B[(k1 + r) * 64 + c];
            }
        }

#pragma unroll
        for (int kk = 0; kk < 16; kk++) {
            float2 a2 = *(const float2*)&As[kk][trow * 2];
            float4 b4 = *(const float4*)&Bs[kk][tcol * 4];
            float bb[4] = {b4.x, b4.y, b4.z, b4.w};
            float aa[2] = {a2.x, a2.y};
#pragma unroll
            for (int i = 0; i < 2; i++)
#pragma unroll
                for (int j = 0; j < 4; j++)
                    acc[i][j] += aa[i] * bb[j];
        }
        __syncthreads();
    }

#pragma unroll
    for (int i = 0; i < 2; i++) {
        int row = m0 + trow * 2 + i;
        if (row < N_NODES) {
            __half2 p0 = __floats2half2_rn(acc[i][0], acc[i][1]);
            __half2 p1 = __floats2half2_rn(acc[i][2], acc[i][3]);
            uint2 u;
            u.x = *reinterpret_cast<unsigned*>(&p0);
            u.y = *reinterpret_cast<unsigned*>(&p1);
            *(uint2*)&g_h2h[row * H2 + tcol * 4] = u;
        }
    }
    float asv[4], adv[4];
#pragma unroll
    for (int j = 0; j < 4; j++) {
        asv[j] = a_src[tcol * 4 + j];
        adv[j] = a_dst[tcol * 4 + j];
    }
#pragma unroll
    for (int i = 0; i < 2; i++) {
        float ds = 0.f, dd = 0.f;
#pragma unroll
        for (int j = 0; j < 4; j++) {
            ds += acc[i][j] * asv[j];
            dd += acc[i][j] * adv[j];
        }
#pragma unroll
        for (int off = 8; off; off >>= 1) {
            ds += __shfl_xor_sync(FULLMASK, ds, off);
            dd += __shfl_xor_sync(FULLMASK, dd, off);
        }
        int row = m0 + trow * 2 + i;
        if (tcol == 0 && row < N_NODES) {
            g_as[row] = ds;
            g_ad[row] = dd;
        }
    }
}

// ---------------- GAT aggregation layer 1 (H=128): warp per node ------------
__global__ void __launch_bounds__(128) gat_agg1_kernel(const float* __restrict__ bias) {
    const __half* hb = g_h1h;
    float* out = g_x1;

    int i = (blockIdx.x * blockDim.x + threadIdx.x) >> 5;
    if (i >= N_NODES) return;
    int lane = threadIdx.x & 31;

    float adi = g_ad[i];
    int deg = g_cnt[i];
    if (deg > CAP) deg = CAP;
    const int* row = &g_csr[i * CAP];

    float es = __expf(leaky(g_as[i] + adi));
    float zl = (lane == 0) ? es : 0.f;
    float acc[4];
    {
        uint2 u = *(const uint2*)&hb[i * H1 + lane * 4];
        float2 f0 = __half22float2(*reinterpret_cast<const __half2*>(&u.x));
        float2 f1 = __half22float2(*reinterpret_cast<const __half2*>(&u.y));
        acc[0] = es * f0.x; acc[1] = es * f0.y;
        acc[2] = es * f1.x; acc[3] = es * f1.y;
    }

    for (int base = 0; base < deg; base += 32) {
        int rem = deg - base;
        if (rem > 32) rem = 32;

        int   idx = 0;
        float e   = 0.f;
        if (lane < rem) {
            idx = __ldg(&row[base + lane]);
            e   = __expf(leaky(__ldg(&g_as[idx]) + adi));
        }
        zl += e;

        int k = 0;
        for (; k + 4 <= rem; k += 4) {
            int   s0 = __shfl_sync(FULLMASK, idx, k);
            int   s1 = __shfl_sync(FULLMASK, idx, k + 1);
            int   s2 = __shfl_sync(FULLMASK, idx, k + 2);
            int   s3 = __shfl_sync(FULLMASK, idx, k + 3);
            float w0 = __shfl_sync(FULLMASK, e, k);
            float w1 = __shfl_sync(FULLMASK, e, k + 1);
            float w2 = __shfl_sync(FULLMASK, e, k + 2);
            float w3 = __shfl_sync(FULLMASK, e, k + 3);
            uint2 u0 = *(const uint2*)&hb[s0 * H1 + lane * 4];
            uint2 u1 = *(const uint2*)&hb[s1 * H1 + lane * 4];
            uint2 u2 = *(const uint2*)&hb[s2 * H1 + lane * 4];
            uint2 u3 = *(const uint2*)&hb[s3 * H1 + lane * 4];
            float2 a0 = __half22float2(*reinterpret_cast<const __half2*>(&u0.x));
            float2 b0 = __half22float2(*reinterpret_cast<const __half2*>(&u0.y));
            float2 a1 = __half22float2(*reinterpret_cast<const __half2*>(&u1.x));
            float2 b1 = __half22float2(*reinterpret_cast<const __half2*>(&u1.y));
            float2 a2 = __half22float2(*reinterpret_cast<const __half2*>(&u2.x));
            float2 b2 = __half22float2(*reinterpret_cast<const __half2*>(&u2.y));
            float2 a3 = __half22float2(*reinterpret_cast<const __half2*>(&u3.x));
            float2 b3 = __half22float2(*reinterpret_cast<const __half2*>(&u3.y));
            acc[0] += w0 * a0.x + w1 * a1.x + w2 * a2.x + w3 * a3.x;
            acc[1] += w0 * a0.y + w1 * a1.y + w2 * a2.y + w3 * a3.y;
            acc[2] += w0 * b0.x + w1 * b1.x + w2 * b2.x + w3 * b3.x;
            acc[3] += w0 * b0.y + w1 * b1.y + w2 * b2.y + w3 * b3.y;
        }
        for (; k < rem; ++k) {
            int   s0 = __shfl_sync(FULLMASK, idx, k);
            float w0 = __shfl_sync(FULLMASK, e, k);
            uint2 u0 = *(const uint2*)&hb[s0 * H1 + lane * 4];
            float2 a0 = __half22float2(*reinterpret_cast<const __half2*>(&u0.x));
            float2 b0 = __half22float2(*reinterpret_cast<const __half2*>(&u0.y));
            acc[0] += w0 * a0.x; acc[1] += w0 * a0.y;
            acc[2] += w0 * b0.x; acc[3] += w0 * b0.y;
        }
    }

#pragma unroll
    for (int off = 16; off; off >>= 1) zl += __shfl_xor_sync(FULLMASK, zl, off);

    float inv = 1.f / zl;
#pragma unroll
    for (int v = 0; v < 4; v++) {
        float r = acc[v] * inv + bias[lane * 4 + v];
        out[i * H1 + lane * 4 + v] = r > 0.f ? r : 0.f;
    }
}

// ---------------- agg layer 2 (H=64) FUSED with projection ------------------
// 256 threads = 8 warps = 8 nodes/block; 1250 blocks cover exactly 10000 nodes.
// After computing relu(x2_row) in registers, projects through Wp (smem) + bp
// and writes d_out directly. Also resets g_cnt for graph-replay invariance.
__global__ void __launch_bounds__(256) gat_agg2_proj_kernel(
        const float* __restrict__ bias, const float* __restrict__ Wp,
        const float* __restrict__ bp, float* __restrict__ outp) {
    __shared__ __align__(16) float Wps[H2 * EMB];   // 16 KB
    const int tid = threadIdx.x;

    // cooperative Wp load: 4096 floats / 256 threads = 4 float4 each
#pragma unroll
    for (int u = 0; u < 4; u++) {
        int idx = tid + u * 256;
        *(float4*)&Wps[idx * 4] = *(const float4*)&Wp[idx * 4];
    }
    __syncthreads();

    int i = (blockIdx.x * blockDim.x + tid) >> 5;
    if (i >= N_NODES) return;
    int lane = tid & 31;

    const __half* hb = g_h2h;
    float adi = g_ad[i];
    int deg = g_cnt[i];
    if (lane == 0) g_cnt[i] = 0;          // reset for next launch (last reader)
    if (deg > CAP) deg = CAP;
    const int* row = &g_csr[i * CAP];

    float es = __expf(leaky(g_as[i] + adi));
    float zl = (lane == 0) ? es : 0.f;
    float acc0, acc1;
    {
        float2 f = __half22float2(*(const __half2*)&hb[i * H2 + lane * 2]);
        acc0 = es * f.x; acc1 = es * f.y;
    }

    for (int base = 0; base < deg; base += 32) {
        int rem = deg - base;
        if (rem > 32) rem = 32;

        int   idx = 0;
        float e   = 0.f;
        if (lane < rem) {
            idx = __ldg(&row[base + lane]);
            e   = __expf(leaky(__ldg(&g_as[idx]) + adi));
        }
        zl += e;

        int k = 0;
        for (; k + 4 <= rem; k += 4) {
            int   s0 = __shfl_sync(FULLMASK, idx, k);
            int   s1 = __shfl_sync(FULLMASK, idx, k + 1);
            int   s2 = __shfl_sync(FULLMASK, idx, k + 2);
            int   s3 = __shfl_sync(FULLMASK, idx, k + 3);
            float w0 = __shfl_sync(FULLMASK, e, k);
            float w1 = __shfl_sync(FULLMASK, e, k + 1);
            float w2 = __shfl_sync(FULLMASK, e, k + 2);
            float w3 = __shfl_sync(FULLMASK, e, k + 3);
            float2 f0 = __half22float2(*(const __half2*)&hb[s0 * H2 + lane * 2]);
            float2 f1 = __half22float2(*(const __half2*)&hb[s1 * H2 + lane * 2]);
            float2 f2 = __half22float2(*(const __half2*)&hb[s2 * H2 + lane * 2]);
            float2 f3 = __half22float2(*(const __half2*)&hb[s3 * H2 + lane * 2]);
            acc0 += w0 * f0.x + w1 * f1.x + w2 * f2.x + w3 * f3.x;
            acc1 += w0 * f0.y + w1 * f1.y + w2 * f2.y + w3 * f3.y;
        }
        for (; k < rem; ++k) {
            int   s0 = __shfl_sync(FULLMASK, idx, k);
            float w0 = __shfl_sync(FULLMASK, e, k);
            float2 f0 = __half22float2(*(const __half2*)&hb[s0 * H2 + lane * 2]);
            acc0 += w0 * f0.x; acc1 += w0 * f0.y;
        }
    }

#pragma unroll
    for (int off = 16; off; off >>= 1) zl += __shfl_xor_sync(FULLMASK, zl, off);

    float inv = 1.f / zl;
    // x2 row values held by this lane: features 2*lane, 2*lane+1
    float v0 = acc0 * inv + bias[lane * 2];
    float v1 = acc1 * inv + bias[lane * 2 + 1];
    v0 = v0 > 0.f ? v0 : 0.f;
    v1 = v1 > 0.f ? v1 : 0.f;

    // projection: out[c] = sum_k x2[k] * Wp[k][c] + bp[c]; lane owns c=2l,2l+1
    float2 ob = *(const float2*)&bp[lane * 2];
    float o0 = ob.x, o1 = ob.y;
#pragma unroll 8
    for (int j = 0; j < 32; j++) {
        float x0 = __shfl_sync(FULLMASK, v0, j);   // feature 2j
        float x1 = __shfl_sync(FULLMASK, v1, j);   // feature 2j+1
        float2 w0 = *(const float2*)&Wps[(2 * j) * EMB + lane * 2];
        float2 w1 = *(const float2*)&Wps[(2 * j + 1) * EMB + lane * 2];
        o0 += x0 * w0.x + x1 * w1.x;
        o1 += x0 * w0.y + x1 * w1.y;
    }
    *(float2*)&outp[i * EMB + lane * 2] = make_float2(o0, o1);
}

// ---------------- launch -----------------------------------------------------
extern "C" void kernel_launch(void* const* d_in, const int* in_sizes, int n_in,
                              void* d_out, int out_size) {
    const float* x    = (const float*)d_in[0];
    const int*   ei   = (const int*)d_in[1];       // int32 edge_index [2, E]
    const float* W1   = (const float*)d_in[2];
    const float* a_s1 = (const float*)d_in[3];
    const float* a_d1 = (const float*)d_in[4];
    const float* b1   = (const float*)d_in[5];
    const float* W2   = (const float*)d_in[6];
    const float* a_s2 = (const float*)d_in[7];
    const float* a_d2 = (const float*)d_in[8];
    const float* b2   = (const float*)d_in[9];
    const float* Wp   = (const float*)d_in[10];
    const float* bp   = (const float*)d_in[11];
    const int E = in_sizes[1] / 2;

    const int TB = 256;
    const int gemmBlocks = (N_NODES + 31) / 32;            // 313
    const int fillBlocks = (E + TB * 2 - 1) / (TB * 2);    // 1250 @ E=640k
    const int agg1Blocks = (N_NODES * 32 + 127) / 128;     // block=128
    const int agg2Blocks = (N_NODES * 32 + TB - 1) / TB;   // block=256

    // fused: gemm1 (h1 + dots) || CSR fill — independent work, one launch
    fused_fill_gemm1_kernel<<<gemmBlocks + fillBlocks, TB>>>(
        ei, E, x, W1, a_s1, a_d1, gemmBlocks);

    // layer-1 aggregation: x1 = relu(softmax-agg(h1) + b1)
    gat_agg1_kernel<<<agg1Blocks, 128>>>(b1);

    // layer-2 GEMM: h2(fp16) = x1 @ W2 (+direct dots)
    gemm2_kernel<<<gemmBlocks, TB>>>(W2, a_s2, a_d2);

    // layer-2 aggregation fused with projection: d_out = relu(agg(h2)+b2) @ Wp + bp
    gat_agg2_proj_kernel<<<agg2Blocks, TB>>>(b2, Wp, bp, (float*)d_out);
}

// round 16
// speedup vs baseline: 1.6396x; 1.0155x over previous
#include <cuda_runtime.h>
#include <cuda_fp16.h>

#define N_NODES 10000
#define D_IN    128
#define H1      128
#define H2      64
#define EMB     64
#define CAP     256      // fixed bucket capacity per destination node
#define NEG_SLOPE 0.2f
#define FULLMASK 0xffffffffu

// ---------------- scratch (device globals; no allocation allowed) -----------
__device__ __half g_h1h[N_NODES * H1];   // GEMM outputs stored fp16 (gather payload)
__device__ __half g_h2h[N_NODES * H2];
__device__ float  g_x1[N_NODES * H1];    // agg output (GEMM A operand)
__device__ float  g_as[N_NODES];
__device__ float  g_ad[N_NODES];
__device__ int    g_cnt[N_NODES];        // zero-init at load; agg2 resets -> launch-invariant
__device__ int    g_csr[N_NODES * CAP];  // bucket CSR: row i at i*CAP

__device__ __forceinline__ float leaky(float x) {
    return x > 0.f ? x : NEG_SLOPE * x;
}

// ---------------- fused: gemm1 (blocks [0, gemmBlocks)) + CSR fill (rest) ----
__global__ void __launch_bounds__(256) fused_fill_gemm1_kernel(
        const int* __restrict__ ei, int E,
        const float* __restrict__ A, const float* __restrict__ B,
        const float* __restrict__ a_src, const float* __restrict__ a_dst,
        int gemmBlocks) {
    const int tid = threadIdx.x;

    if (blockIdx.x >= gemmBlocks) {
        // ---------------- CSR fill path ----------------
        int t = (blockIdx.x - gemmBlocks) * blockDim.x + tid;
        int e0 = t * 2;
        if (e0 >= E) return;
        if (e0 + 2 <= E && ((E & 1) == 0)) {
            int2 s2 = *(const int2*)&ei[e0];
            int2 d2 = *(const int2*)&ei[E + e0];
            int p0 = ((unsigned)d2.x < N_NODES) ? atomicAdd(&g_cnt[d2.x], 1) : CAP;
            int p1 = ((unsigned)d2.y < N_NODES) ? atomicAdd(&g_cnt[d2.y], 1) : CAP;
            if (p0 < CAP && (unsigned)s2.x < N_NODES) g_csr[d2.x * CAP + p0] = s2.x;
            if (p1 < CAP && (unsigned)s2.y < N_NODES) g_csr[d2.y * CAP + p1] = s2.y;
        } else {
            for (int e = e0; e < E && e < e0 + 2; e++) {
                int s = ei[e];
                int d = ei[E + e];
                if ((unsigned)s < N_NODES && (unsigned)d < N_NODES) {
                    int pos = atomicAdd(&g_cnt[d], 1);
                    if (pos < CAP) g_csr[d * CAP + pos] = s;
                }
            }
        }
        return;
    }

    // ---------------- gemm1 path ----------------
    __shared__ __align__(16) float As[16][34];
    __shared__ __align__(16) float Bs[16][128];
    const int trow = tid >> 4;                   // 0..15
    const int tcol = tid & 15;                   // 0..15
    const int m0 = blockIdx.x * 32;
    float acc[2][8] = {};

    float aR[2], bR[8];
#pragma unroll
    for (int u = 0; u < 2; u++) {
        int idx = tid + u * 256, r = idx >> 4, c = idx & 15, gr = m0 + r;
        aR[u] = (gr < N_NODES) ? A[gr * D_IN + c] : 0.f;
    }
#pragma unroll
    for (int u = 0; u < 8; u++) {
        int idx = tid + u * 256, r = idx >> 7, c = idx & 127;
        bR[u] = B[r * H1 + c];
    }

    for (int k0 = 0; k0 < D_IN; k0 += 16) {
#pragma unroll
        for (int u = 0; u < 2; u++) {
            int idx = tid + u * 256, r = idx >> 4, c = idx & 15;
            As[c][r] = aR[u];
        }
#pragma unroll
        for (int u = 0; u < 8; u++) {
            int idx = tid + u * 256, r = idx >> 7, c = idx & 127;
            Bs[r][c] = bR[u];
        }
        __syncthreads();

        int k1 = k0 + 16;
        if (k1 < D_IN) {
#pragma unroll
            for (int u = 0; u < 2; u++) {
                int idx = tid + u * 256, r = idx >> 4, c = idx & 15, gr = m0 + r;
                aR[u] = (gr < N_NODES) ? A[gr * D_IN + k1 + c] : 0.f;
            }
#pragma unroll
            for (int u = 0; u < 8; u++) {
                int idx = tid + u * 256, r = idx >> 7, c = idx & 127;
                bR[u] = B[(k1 + r) * H1 + c];
            }
        }

#pragma unroll
        for (int kk = 0; kk < 16; kk++) {
            float2 a2 = *(const float2*)&As[kk][trow * 2];
            float4 b0 = *(const float4*)&Bs[kk][tcol * 8];
            float4 b1 = *(const float4*)&Bs[kk][tcol * 8 + 4];
            float bb[8] = {b0.x, b0.y, b0.z, b0.w, b1.x, b1.y, b1.z, b1.w};
            float aa[2] = {a2.x, a2.y};
#pragma unroll
            for (int i = 0; i < 2; i++)
#pragma unroll
                for (int j = 0; j < 8; j++)
                    acc[i][j] += aa[i] * bb[j];
        }
        __syncthreads();
    }

#pragma unroll
    for (int i = 0; i < 2; i++) {
        int row = m0 + trow * 2 + i;
        if (row < N_NODES) {
            __half2 p0 = __floats2half2_rn(acc[i][0], acc[i][1]);
            __half2 p1 = __floats2half2_rn(acc[i][2], acc[i][3]);
            __half2 p2 = __floats2half2_rn(acc[i][4], acc[i][5]);
            __half2 p3 = __floats2half2_rn(acc[i][6], acc[i][7]);
            uint4 u;
            u.x = *reinterpret_cast<unsigned*>(&p0);
            u.y = *reinterpret_cast<unsigned*>(&p1);
            u.z = *reinterpret_cast<unsigned*>(&p2);
            u.w = *reinterpret_cast<unsigned*>(&p3);
            *(uint4*)&g_h1h[row * H1 + tcol * 8] = u;
        }
    }

    float asv[8], adv[8];
#pragma unroll
    for (int j = 0; j < 8; j++) {
        asv[j] = a_src[tcol * 8 + j];
        adv[j] = a_dst[tcol * 8 + j];
    }
#pragma unroll
    for (int i = 0; i < 2; i++) {
        float ds = 0.f, dd = 0.f;
#pragma unroll
        for (int j = 0; j < 8; j++) {
            ds += acc[i][j] * asv[j];
            dd += acc[i][j] * adv[j];
        }
#pragma unroll
        for (int off = 8; off; off >>= 1) {
            ds += __shfl_xor_sync(FULLMASK, ds, off);
            dd += __shfl_xor_sync(FULLMASK, dd, off);
        }
        int row = m0 + trow * 2 + i;
        if (tcol == 0 && row < N_NODES) {
            g_as[row] = ds;
            g_ad[row] = dd;
        }
    }
}

// ---------------- gemm2: h2(fp16) = x1 @ W2, 32x64 tile, double-buffered -----
__global__ void __launch_bounds__(256) gemm2_kernel(
        const float* __restrict__ B,
        const float* __restrict__ a_src, const float* __restrict__ a_dst) {
    const float* A = g_x1;
    __shared__ __align__(16) float As[16][34];
    __shared__ __align__(16) float Bs[16][64];
    const int tid  = threadIdx.x;
    const int trow = tid >> 4;
    const int tcol = tid & 15;
    const int m0 = blockIdx.x * 32;
    float acc[2][4] = {};

    float aR[2], bR[4];
#pragma unroll
    for (int u = 0; u < 2; u++) {
        int idx = tid + u * 256, r = idx >> 4, c = idx & 15, gr = m0 + r;
        aR[u] = (gr < N_NODES) ? A[gr * H1 + c] : 0.f;
    }
#pragma unroll
    for (int u = 0; u < 4; u++) {
        int idx = tid + u * 256, r = idx >> 6, c = idx & 63;
        bR[u] = B[r * 64 + c];
    }

    for (int k0 = 0; k0 < H1; k0 += 16) {
#pragma unroll
        for (int u = 0; u < 2; u++) {
            int idx = tid + u * 256, r = idx >> 4, c = idx & 15;
            As[c][r] = aR[u];
        }
#pragma unroll
        for (int u = 0; u < 4; u++) {
            int idx = tid + u * 256, r = idx >> 6, c = idx & 63;
            Bs[r][c] = bR[u];
        }
        __syncthreads();

        int k1 = k0 + 16;
        if (k1 < H1) {
#pragma unroll
            for (int u = 0; u < 2; u++) {
                int idx = tid + u * 256, r = idx >> 4, c = idx & 15, gr = m0 + r;
                aR[u] = (gr < N_NODES) ? A[gr * H1 + k1 + c] : 0.f;
            }
#pragma unroll
            for (int u = 0; u < 4; u++) {
                int idx = tid + u * 256, r = idx >> 6, c = idx & 63;
                bR[u] = B[(k1 + r) * 64 + c];
            }
        }

#pragma unroll
        for (int kk = 0; kk < 16; kk++) {
            float2 a2 = *(const float2*)&As[kk][trow * 2];
            float4 b4 = *(const float4*)&Bs[kk][tcol * 4];
            float bb[4] = {b4.x, b4.y, b4.z, b4.w};
            float aa[2] = {a2.x, a2.y};
#pragma unroll
            for (int i = 0; i < 2; i++)
#pragma unroll
                for (int j = 0; j < 4; j++)
                    acc[i][j] += aa[i] * bb[j];
        }
        __syncthreads();
    }

#pragma unroll
    for (int i = 0; i < 2; i++) {
        int row = m0 + trow * 2 + i;
        if (row < N_NODES) {
            __half2 p0 = __floats2half2_rn(acc[i][0], acc[i][1]);
            __half2 p1 = __floats2half2_rn(acc[i][2], acc[i][3]);
            uint2 u;
            u.x = *reinterpret_cast<unsigned*>(&p0);
            u.y = *reinterpret_cast<unsigned*>(&p1);
            *(uint2*)&g_h2h[row * H2 + tcol * 4] = u;
        }
    }
    float asv[4], adv[4];
#pragma unroll
    for (int j = 0; j < 4; j++) {
        asv[j] = a_src[tcol * 4 + j];
        adv[j] = a_dst[tcol * 4 + j];
    }
#pragma unroll
    for (int i = 0; i < 2; i++) {
        float ds = 0.f, dd = 0.f;
#pragma unroll
        for (int j = 0; j < 4; j++) {
            ds += acc[i][j] * asv[j];
            dd += acc[i][j] * adv[j];
        }
#pragma unroll
        for (int off = 8; off; off >>= 1) {
            ds += __shfl_xor_sync(FULLMASK, ds, off);
            dd += __shfl_xor_sync(FULLMASK, dd, off);
        }
        int row = m0 + trow * 2 + i;
        if (tcol == 0 && row < N_NODES) {
            g_as[row] = ds;
            g_ad[row] = dd;
        }
    }
}

// ---------------- GAT aggregation layer 1 (H=128): warp per node ------------
__global__ void __launch_bounds__(128) gat_agg1_kernel(const float* __restrict__ bias) {
    const __half* hb = g_h1h;
    float* out = g_x1;

    int i = (blockIdx.x * blockDim.x + threadIdx.x) >> 5;
    if (i >= N_NODES) return;
    int lane = threadIdx.x & 31;

    float adi = g_ad[i];
    int deg = g_cnt[i];
    if (deg > CAP) deg = CAP;
    const int* row = &g_csr[i * CAP];

    float es = __expf(leaky(g_as[i] + adi));
    float zl = (lane == 0) ? es : 0.f;
    float acc[4];
    {
        uint2 u = *(const uint2*)&hb[i * H1 + lane * 4];
        float2 f0 = __half22float2(*reinterpret_cast<const __half2*>(&u.x));
        float2 f1 = __half22float2(*reinterpret_cast<const __half2*>(&u.y));
        acc[0] = es * f0.x; acc[1] = es * f0.y;
        acc[2] = es * f1.x; acc[3] = es * f1.y;
    }

    for (int base = 0; base < deg; base += 32) {
        int rem = deg - base;
        if (rem > 32) rem = 32;

        int   idx = 0;
        float e   = 0.f;
        if (lane < rem) {
            idx = __ldg(&row[base + lane]);
            e   = __expf(leaky(__ldg(&g_as[idx]) + adi));
        }
        zl += e;

        int k = 0;
        for (; k + 4 <= rem; k += 4) {
            int   s0 = __shfl_sync(FULLMASK, idx, k);
            int   s1 = __shfl_sync(FULLMASK, idx, k + 1);
            int   s2 = __shfl_sync(FULLMASK, idx, k + 2);
            int   s3 = __shfl_sync(FULLMASK, idx, k + 3);
            float w0 = __shfl_sync(FULLMASK, e, k);
            float w1 = __shfl_sync(FULLMASK, e, k + 1);
            float w2 = __shfl_sync(FULLMASK, e, k + 2);
            float w3 = __shfl_sync(FULLMASK, e, k + 3);
            uint2 u0 = *(const uint2*)&hb[s0 * H1 + lane * 4];
            uint2 u1 = *(const uint2*)&hb[s1 * H1 + lane * 4];
            uint2 u2 = *(const uint2*)&hb[s2 * H1 + lane * 4];
            uint2 u3 = *(const uint2*)&hb[s3 * H1 + lane * 4];
            float2 a0 = __half22float2(*reinterpret_cast<const __half2*>(&u0.x));
            float2 b0 = __half22float2(*reinterpret_cast<const __half2*>(&u0.y));
            float2 a1 = __half22float2(*reinterpret_cast<const __half2*>(&u1.x));
            float2 b1 = __half22float2(*reinterpret_cast<const __half2*>(&u1.y));
            float2 a2 = __half22float2(*reinterpret_cast<const __half2*>(&u2.x));
            float2 b2 = __half22float2(*reinterpret_cast<const __half2*>(&u2.y));
            float2 a3 = __half22float2(*reinterpret_cast<const __half2*>(&u3.x));
            float2 b3 = __half22float2(*reinterpret_cast<const __half2*>(&u3.y));
            acc[0] += w0 * a0.x + w1 * a1.x + w2 * a2.x + w3 * a3.x;
            acc[1] += w0 * a0.y + w1 * a1.y + w2 * a2.y + w3 * a3.y;
            acc[2] += w0 * b0.x + w1 * b1.x + w2 * b2.x + w3 * b3.x;
            acc[3] += w0 * b0.y + w1 * b1.y + w2 * b2.y + w3 * b3.y;
        }
        for (; k < rem; ++k) {
            int   s0 = __shfl_sync(FULLMASK, idx, k);
            float w0 = __shfl_sync(FULLMASK, e, k);
            uint2 u0 = *(const uint2*)&hb[s0 * H1 + lane * 4];
            float2 a0 = __half22float2(*reinterpret_cast<const __half2*>(&u0.x));
            float2 b0 = __half22float2(*reinterpret_cast<const __half2*>(&u0.y));
            acc[0] += w0 * a0.x; acc[1] += w0 * a0.y;
            acc[2] += w0 * b0.x; acc[3] += w0 * b0.y;
        }
    }

#pragma unroll
    for (int off = 16; off; off >>= 1) zl += __shfl_xor_sync(FULLMASK, zl, off);

    float inv = 1.f / zl;
#pragma unroll
    for (int v = 0; v < 4; v++) {
        float r = acc[v] * inv + bias[lane * 4 + v];
        out[i * H1 + lane * 4 + v] = r > 0.f ? r : 0.f;
    }
}

// ---------------- agg layer 2 (H=64) FUSED with projection ------------------
// 256 threads = 8 warps = 8 nodes/block; 1250 blocks cover exactly 10000 nodes.
// Projection via smem-staged x2 row (no shfls, 4 independent FFMA chains).
__global__ void __launch_bounds__(256) gat_agg2_proj_kernel(
        const float* __restrict__ bias, const float* __restrict__ Wp,
        const float* __restrict__ bp, float* __restrict__ outp) {
    __shared__ __align__(16) float Wps[H2 * EMB];   // 16 KB
    __shared__ __align__(16) float x2s[8][64];      // 2 KB (per-warp x2 rows)
    const int tid = threadIdx.x;

#pragma unroll
    for (int u = 0; u < 4; u++) {
        int idx = tid + u * 256;
        *(float4*)&Wps[idx * 4] = *(const float4*)&Wp[idx * 4];
    }
    __syncthreads();

    int i = (blockIdx.x * blockDim.x + tid) >> 5;
    if (i >= N_NODES) return;
    int lane = tid & 31;
    int w = tid >> 5;

    const __half* hb = g_h2h;
    float adi = g_ad[i];
    int deg = g_cnt[i];
    if (lane == 0) g_cnt[i] = 0;          // reset for next launch (last reader)
    if (deg > CAP) deg = CAP;
    const int* row = &g_csr[i * CAP];

    float es = __expf(leaky(g_as[i] + adi));
    float zl = (lane == 0) ? es : 0.f;
    float acc0, acc1;
    {
        float2 f = __half22float2(*(const __half2*)&hb[i * H2 + lane * 2]);
        acc0 = es * f.x; acc1 = es * f.y;
    }

    for (int base = 0; base < deg; base += 32) {
        int rem = deg - base;
        if (rem > 32) rem = 32;

        int   idx = 0;
        float e   = 0.f;
        if (lane < rem) {
            idx = __ldg(&row[base + lane]);
            e   = __expf(leaky(__ldg(&g_as[idx]) + adi));
        }
        zl += e;

        int k = 0;
        for (; k + 4 <= rem; k += 4) {
            int   s0 = __shfl_sync(FULLMASK, idx, k);
            int   s1 = __shfl_sync(FULLMASK, idx, k + 1);
            int   s2 = __shfl_sync(FULLMASK, idx, k + 2);
            int   s3 = __shfl_sync(FULLMASK, idx, k + 3);
            float w0 = __shfl_sync(FULLMASK, e, k);
            float w1 = __shfl_sync(FULLMASK, e, k + 1);
            float w2 = __shfl_sync(FULLMASK, e, k + 2);
            float w3 = __shfl_sync(FULLMASK, e, k + 3);
            float2 f0 = __half22float2(*(const __half2*)&hb[s0 * H2 + lane * 2]);
            float2 f1 = __half22float2(*(const __half2*)&hb[s1 * H2 + lane * 2]);
            float2 f2 = __half22float2(*(const __half2*)&hb[s2 * H2 + lane * 2]);
            float2 f3 = __half22float2(*(const __half2*)&hb[s3 * H2 + lane * 2]);
            acc0 += w0 * f0.x + w1 * f1.x + w2 * f2.x + w3 * f3.x;
            acc1 += w0 * f0.y + w1 * f1.y + w2 * f2.y + w3 * f3.y;
        }
        for (; k < rem; ++k) {
            int   s0 = __shfl_sync(FULLMASK, idx, k);
            float w0 = __shfl_sync(FULLMASK, e, k);
            float2 f0 = __half22float2(*(const __half2*)&hb[s0 * H2 + lane * 2]);
            acc0 += w0 * f0.x; acc1 += w0 * f0.y;
        }
    }

#pragma unroll
    for (int off = 16; off; off >>= 1) zl += __shfl_xor_sync(FULLMASK, zl, off);

    float inv = 1.f / zl;
    float v0 = acc0 * inv + bias[lane * 2];
    float v1 = acc1 * inv + bias[lane * 2 + 1];
    v0 = v0 > 0.f ? v0 : 0.f;
    v1 = v1 > 0.f ? v1 : 0.f;

    // stage x2 row in smem (warp-private), then shfl-free projection
    *(float2*)&x2s[w][lane * 2] = make_float2(v0, v1);
    __syncwarp();

    float2 ob = *(const float2*)&bp[lane * 2];
    float oa0 = ob.x, oa1 = ob.y;         // chains A (even k-groups)
    float ob0 = 0.f, ob1 = 0.f;           // chains B (odd k-groups)
#pragma unroll
    for (int j = 0; j < 16; j++) {
        float4 xv = *(const float4*)&x2s[w][j * 4];   // broadcast LDS.128
        float2 w0 = *(const float2*)&Wps[(4 * j + 0) * EMB + lane * 2];
        float2 w1 = *(const float2*)&Wps[(4 * j + 1) * EMB + lane * 2];
        float2 w2 = *(const float2*)&Wps[(4 * j + 2) * EMB + lane * 2];
        float2 w3 = *(const float2*)&Wps[(4 * j + 3) * EMB + lane * 2];
        oa0 += xv.x * w0.x + xv.z * w2.x;
        oa1 += xv.x * w0.y + xv.z * w2.y;
        ob0 += xv.y * w1.x + xv.w * w3.x;
        ob1 += xv.y * w1.y + xv.w * w3.y;
    }
    *(float2*)&outp[i * EMB + lane * 2] = make_float2(oa0 + ob0, oa1 + ob1);
}

// ---------------- launch -----------------------------------------------------
extern "C" void kernel_launch(void* const* d_in, const int* in_sizes, int n_in,
                              void* d_out, int out_size) {
    const float* x    = (const float*)d_in[0];
    const int*   ei   = (const int*)d_in[1];       // int32 edge_index [2, E]
    const float* W1   = (const float*)d_in[2];
    const float* a_s1 = (const float*)d_in[3];
    const float* a_d1 = (const float*)d_in[4];
    const float* b1   = (const float*)d_in[5];
    const float* W2   = (const float*)d_in[6];
    const float* a_s2 = (const float*)d_in[7];
    const float* a_d2 = (const float*)d_in[8];
    const float* b2   = (const float*)d_in[9];
    const float* Wp   = (const float*)d_in[10];
    const float* bp   = (const float*)d_in[11];
    const int E = in_sizes[1] / 2;

    const int TB = 256;
    const int gemmBlocks = (N_NODES + 31) / 32;            // 313
    const int fillBlocks = (E + TB * 2 - 1) / (TB * 2);    // 1250 @ E=640k
    const int agg1Blocks = (N_NODES * 32 + 127) / 128;     // block=128
    const int agg2Blocks = (N_NODES * 32 + TB - 1) / TB;   // block=256

    // fused: gemm1 (h1 + dots) || CSR fill — independent work, one launch
    fused_fill_gemm1_kernel<<<gemmBlocks + fillBlocks, TB>>>(
        ei, E, x, W1, a_s1, a_d1, gemmBlocks);

    // layer-1 aggregation: x1 = relu(softmax-agg(h1) + b1)
    gat_agg1_kernel<<<agg1Blocks, 128>>>(b1);

    // layer-2 GEMM: h2(fp16) = x1 @ W2 (+direct dots)
    gemm2_kernel<<<gemmBlocks, TB>>>(W2, a_s2, a_d2);

    // layer-2 aggregation fused with projection: d_out = relu(agg(h2)+b2) @ Wp + bp
    gat_agg2_proj_kernel<<<agg2Blocks, TB>>>(b2, Wp, bp, (float*)d_out);
}

// round 17
// speedup vs baseline: 1.6809x; 1.0252x over previous
#include <cuda_runtime.h>
#include <cuda_fp16.h>

#define N_NODES 10000
#define D_IN    128
#define H1      128
#define H2      64
#define EMB     64
#define CAP     256      // fixed bucket capacity per destination node
#define NEG_SLOPE 0.2f
#define FULLMASK 0xffffffffu

// ---------------- scratch (device globals; no allocation allowed) -----------
__device__ __half g_h1h[N_NODES * H1];   // GEMM outputs stored fp16 (gather payload)
__device__ __half g_h2h[N_NODES * H2];
__device__ float  g_x1[N_NODES * H1];    // agg output (GEMM A operand)
__device__ float  g_as[N_NODES];
__device__ float  g_ad[N_NODES];
__device__ int    g_cnt[N_NODES];        // zero-init at load; agg2 resets -> launch-invariant
__device__ int    g_csr[N_NODES * CAP];  // bucket CSR: row i at i*CAP

__device__ __forceinline__ float leaky(float x) {
    return x > 0.f ? x : NEG_SLOPE * x;
}

// ---------------- fused: gemm1 (blocks [0, gemmBlocks)) + CSR fill (rest) ----
__global__ void __launch_bounds__(256) fused_fill_gemm1_kernel(
        const int* __restrict__ ei, int E,
        const float* __restrict__ A, const float* __restrict__ B,
        const float* __restrict__ a_src, const float* __restrict__ a_dst,
        int gemmBlocks) {
    const int tid = threadIdx.x;

    if (blockIdx.x >= gemmBlocks) {
        // ---------------- CSR fill path ----------------
        int t = (blockIdx.x - gemmBlocks) * blockDim.x + tid;
        int e0 = t * 2;
        if (e0 >= E) return;
        if (e0 + 2 <= E && ((E & 1) == 0)) {
            int2 s2 = *(const int2*)&ei[e0];
            int2 d2 = *(const int2*)&ei[E + e0];
            int p0 = ((unsigned)d2.x < N_NODES) ? atomicAdd(&g_cnt[d2.x], 1) : CAP;
            int p1 = ((unsigned)d2.y < N_NODES) ? atomicAdd(&g_cnt[d2.y], 1) : CAP;
            if (p0 < CAP && (unsigned)s2.x < N_NODES) g_csr[d2.x * CAP + p0] = s2.x;
            if (p1 < CAP && (unsigned)s2.y < N_NODES) g_csr[d2.y * CAP + p1] = s2.y;
        } else {
            for (int e = e0; e < E && e < e0 + 2; e++) {
                int s = ei[e];
                int d = ei[E + e];
                if ((unsigned)s < N_NODES && (unsigned)d < N_NODES) {
                    int pos = atomicAdd(&g_cnt[d], 1);
                    if (pos < CAP) g_csr[d * CAP + pos] = s;
                }
            }
        }
        return;
    }

    // ---------------- gemm1 path ----------------
    __shared__ __align__(16) float As[16][34];
    __shared__ __align__(16) float Bs[16][128];
    const int trow = tid >> 4;                   // 0..15
    const int tcol = tid & 15;                   // 0..15
    const int m0 = blockIdx.x * 32;
    float acc[2][8] = {};

    float aR[2], bR[8];
#pragma unroll
    for (int u = 0; u < 2; u++) {
        int idx = tid + u * 256, r = idx >> 4, c = idx & 15, gr = m0 + r;
        aR[u] = (gr < N_NODES) ? A[gr * D_IN + c] : 0.f;
    }
#pragma unroll
    for (int u = 0; u < 8; u++) {
        int idx = tid + u * 256, r = idx >> 7, c = idx & 127;
        bR[u] = B[r * H1 + c];
    }

    for (int k0 = 0; k0 < D_IN; k0 += 16) {
#pragma unroll
        for (int u = 0; u < 2; u++) {
            int idx = tid + u * 256, r = idx >> 4, c = idx & 15;
            As[c][r] = aR[u];
        }
#pragma unroll
        for (int u = 0; u < 8; u++) {
            int idx = tid + u * 256, r = idx >> 7, c = idx & 127;
            Bs[r][c] = bR[u];
        }
        __syncthreads();

        int k1 = k0 + 16;
        if (k1 < D_IN) {
#pragma unroll
            for (int u = 0; u < 2; u++) {
                int idx = tid + u * 256, r = idx >> 4, c = idx & 15, gr = m0 + r;
                aR[u] = (gr < N_NODES) ? A[gr * D_IN + k1 + c] : 0.f;
            }
#pragma unroll
            for (int u = 0; u < 8; u++) {
                int idx = tid + u * 256, r = idx >> 7, c = idx & 127;
                bR[u] = B[(k1 + r) * H1 + c];
            }
        }

#pragma unroll
        for (int kk = 0; kk < 16; kk++) {
            float2 a2 = *(const float2*)&As[kk][trow * 2];
            float4 b0 = *(const float4*)&Bs[kk][tcol * 8];
            float4 b1 = *(const float4*)&Bs[kk][tcol * 8 + 4];
            float bb[8] = {b0.x, b0.y, b0.z, b0.w, b1.x, b1.y, b1.z, b1.w};
            float aa[2] = {a2.x, a2.y};
#pragma unroll
            for (int i = 0; i < 2; i++)
#pragma unroll
                for (int j = 0; j < 8; j++)
                    acc[i][j] += aa[i] * bb[j];
        }
        __syncthreads();
    }

#pragma unroll
    for (int i = 0; i < 2; i++) {
        int row = m0 + trow * 2 + i;
        if (row < N_NODES) {
            __half2 p0 = __floats2half2_rn(acc[i][0], acc[i][1]);
            __half2 p1 = __floats2half2_rn(acc[i][2], acc[i][3]);
            __half2 p2 = __floats2half2_rn(acc[i][4], acc[i][5]);
            __half2 p3 = __floats2half2_rn(acc[i][6], acc[i][7]);
            uint4 u;
            u.x = *reinterpret_cast<unsigned*>(&p0);
            u.y = *reinterpret_cast<unsigned*>(&p1);
            u.z = *reinterpret_cast<unsigned*>(&p2);
            u.w = *reinterpret_cast<unsigned*>(&p3);
            *(uint4*)&g_h1h[row * H1 + tcol * 8] = u;
        }
    }

    float asv[8], adv[8];
#pragma unroll
    for (int j = 0; j < 8; j++) {
        asv[j] = a_src[tcol * 8 + j];
        adv[j] = a_dst[tcol * 8 + j];
    }
#pragma unroll
    for (int i = 0; i < 2; i++) {
        float ds = 0.f, dd = 0.f;
#pragma unroll
        for (int j = 0; j < 8; j++) {
            ds += acc[i][j] * asv[j];
            dd += acc[i][j] * adv[j];
        }
#pragma unroll
        for (int off = 8; off; off >>= 1) {
            ds += __shfl_xor_sync(FULLMASK, ds, off);
            dd += __shfl_xor_sync(FULLMASK, dd, off);
        }
        int row = m0 + trow * 2 + i;
        if (tcol == 0 && row < N_NODES) {
            g_as[row] = ds;
            g_ad[row] = dd;
        }
    }
}

// ---------------- gemm2: h2(fp16) = x1 @ W2, 32x64 tile, double-buffered -----
__global__ void __launch_bounds__(256) gemm2_kernel(
        const float* __restrict__ B,
        const float* __restrict__ a_src, const float* __restrict__ a_dst) {
    const float* A = g_x1;
    __shared__ __align__(16) float As[16][34];
    __shared__ __align__(16) float Bs[16][64];
    const int tid  = threadIdx.x;
    const int trow = tid >> 4;
    const int tcol = tid & 15;
    const int m0 = blockIdx.x * 32;
    float acc[2][4] = {};

    float aR[2], bR[4];
#pragma unroll
    for (int u = 0; u < 2; u++) {
        int idx = tid + u * 256, r = idx >> 4, c = idx & 15, gr = m0 + r;
        aR[u] = (gr < N_NODES) ? A[gr * H1 + c] : 0.f;
    }
#pragma unroll
    for (int u = 0; u < 4; u++) {
        int idx = tid + u * 256, r = idx >> 6, c = idx & 63;
        bR[u] = B[r * 64 + c];
    }

    for (int k0 = 0; k0 < H1; k0 += 16) {
#pragma unroll
        for (int u = 0; u < 2; u++) {
            int idx = tid + u * 256, r = idx >> 4, c = idx & 15;
            As[c][r] = aR[u];
        }
#pragma unroll
        for (int u = 0; u < 4; u++) {
            int idx = tid + u * 256, r = idx >> 6, c = idx & 63;
            Bs[r][c] = bR[u];
        }
        __syncthreads();

        int k1 = k0 + 16;
        if (k1 < H1) {
#pragma unroll
            for (int u = 0; u < 2; u++) {
                int idx = tid + u * 256, r = idx >> 4, c = idx & 15, gr = m0 + r;
                aR[u] = (gr < N_NODES) ? A[gr * H1 + k1 + c] : 0.f;
            }
#pragma unroll
            for (int u = 0; u < 4; u++) {
                int idx = tid + u * 256, r = idx >> 6, c = idx & 63;
                bR[u] = B[(k1 + r) * 64 + c];
            }
        }

#pragma unroll
        for (int kk = 0; kk < 16; kk++) {
            float2 a2 = *(const float2*)&As[kk][trow * 2];
            float4 b4 = *(const float4*)&Bs[kk][tcol * 4];
            float bb[4] = {b4.x, b4.y, b4.z, b4.w};
            float aa[2] = {a2.x, a2.y};
#pragma unroll
            for (int i = 0; i < 2; i++)
#pragma unroll
                for (int j = 0; j < 4; j++)
                    acc[i][j] += aa[i] * bb[j];
        }
        __syncthreads();
    }

#pragma unroll
    for (int i = 0; i < 2; i++) {
        int row = m0 + trow * 2 + i;
        if (row < N_NODES) {
            __half2 p0 = __floats2half2_rn(acc[i][0], acc[i][1]);
            __half2 p1 = __floats2half2_rn(acc[i][2], acc[i][3]);
            uint2 u;
            u.x = *reinterpret_cast<unsigned*>(&p0);
            u.y = *reinterpret_cast<unsigned*>(&p1);
            *(uint2*)&g_h2h[row * H2 + tcol * 4] = u;
        }
    }
    float asv[4], adv[4];
#pragma unroll
    for (int j = 0; j < 4; j++) {
        asv[j] = a_src[tcol * 4 + j];
        adv[j] = a_dst[tcol * 4 + j];
    }
#pragma unroll
    for (int i = 0; i < 2; i++) {
        float ds = 0.f, dd = 0.f;
#pragma unroll
        for (int j = 0; j < 4; j++) {
            ds += acc[i][j] * asv[j];
            dd += acc[i][j] * adv[j];
        }
#pragma unroll
        for (int off = 8; off; off >>= 1) {
            ds += __shfl_xor_sync(FULLMASK, ds, off);
            dd += __shfl_xor_sync(FULLMASK, dd, off);
        }
        int row = m0 + trow * 2 + i;
        if (tcol == 0 && row < N_NODES) {
            g_as[row] = ds;
            g_ad[row] = dd;
        }
    }
}

// ---------------- GAT aggregation layer 1 (H=128): warp per node ------------
// Software-pipelined weight chain: next chunk's (idx, g_as) prefetched before
// the current chunk's feature loop, hiding the dependent-gather latency.
__global__ void __launch_bounds__(128) gat_agg1_kernel(const float* __restrict__ bias) {
    const __half* hb = g_h1h;
    float* out = g_x1;

    int i = (blockIdx.x * blockDim.x + threadIdx.x) >> 5;
    if (i >= N_NODES) return;
    int lane = threadIdx.x & 31;

    float adi = g_ad[i];
    int deg = g_cnt[i];
    if (deg > CAP) deg = CAP;
    const int* row = &g_csr[i * CAP];

    float es = __expf(leaky(g_as[i] + adi));
    float zl = (lane == 0) ? es : 0.f;
    float acc[4];
    {
        uint2 u = *(const uint2*)&hb[i * H1 + lane * 4];
        float2 f0 = __half22float2(*reinterpret_cast<const __half2*>(&u.x));
        float2 f1 = __half22float2(*reinterpret_cast<const __half2*>(&u.y));
        acc[0] = es * f0.x; acc[1] = es * f0.y;
        acc[2] = es * f1.x; acc[3] = es * f1.y;
    }

    // prefetch chunk 0 weight chain
    int   idxc = 0;
    if (lane < deg) idxc = __ldg(&row[lane]);
    float asc = __ldg(&g_as[idxc]);          // idx 0 is always in bounds

    for (int base = 0; base < deg; base += 32) {
        int rem = deg - base;
        if (rem > 32) rem = 32;

        float e = (lane < rem) ? __expf(leaky(asc + adi)) : 0.f;
        zl += e;

        // prefetch next chunk's (idx, as) — latency hidden by feature loop below
        int   idxn = 0;
        float asn  = 0.f;
        int nbase = base + 32;
        if (nbase < deg) {
            if (lane < deg - nbase) idxn = __ldg(&row[nbase + lane]);
            asn = __ldg(&g_as[idxn]);
        }

        int k = 0;
        for (; k + 4 <= rem; k += 4) {
            int   s0 = __shfl_sync(FULLMASK, idxc, k);
            int   s1 = __shfl_sync(FULLMASK, idxc, k + 1);
            int   s2 = __shfl_sync(FULLMASK, idxc, k + 2);
            int   s3 = __shfl_sync(FULLMASK, idxc, k + 3);
            float w0 = __shfl_sync(FULLMASK, e, k);
            float w1 = __shfl_sync(FULLMASK, e, k + 1);
            float w2 = __shfl_sync(FULLMASK, e, k + 2);
            float w3 = __shfl_sync(FULLMASK, e, k + 3);
            uint2 u0 = *(const uint2*)&hb[s0 * H1 + lane * 4];
            uint2 u1 = *(const uint2*)&hb[s1 * H1 + lane * 4];
            uint2 u2 = *(const uint2*)&hb[s2 * H1 + lane * 4];
            uint2 u3 = *(const uint2*)&hb[s3 * H1 + lane * 4];
            float2 a0 = __half22float2(*reinterpret_cast<const __half2*>(&u0.x));
            float2 b0 = __half22float2(*reinterpret_cast<const __half2*>(&u0.y));
            float2 a1 = __half22float2(*reinterpret_cast<const __half2*>(&u1.x));
            float2 b1 = __half22float2(*reinterpret_cast<const __half2*>(&u1.y));
            float2 a2 = __half22float2(*reinterpret_cast<const __half2*>(&u2.x));
            float2 b2 = __half22float2(*reinterpret_cast<const __half2*>(&u2.y));
            float2 a3 = __half22float2(*reinterpret_cast<const __half2*>(&u3.x));
            float2 b3 = __half22float2(*reinterpret_cast<const __half2*>(&u3.y));
            acc[0] += w0 * a0.x + w1 * a1.x + w2 * a2.x + w3 * a3.x;
            acc[1] += w0 * a0.y + w1 * a1.y + w2 * a2.y + w3 * a3.y;
            acc[2] += w0 * b0.x + w1 * b1.x + w2 * b2.x + w3 * b3.x;
            acc[3] += w0 * b0.y + w1 * b1.y + w2 * b2.y + w3 * b3.y;
        }
        for (; k < rem; ++k) {
            int   s0 = __shfl_sync(FULLMASK, idxc, k);
            float w0 = __shfl_sync(FULLMASK, e, k);
            uint2 u0 = *(const uint2*)&hb[s0 * H1 + lane * 4];
            float2 a0 = __half22float2(*reinterpret_cast<const __half2*>(&u0.x));
            float2 b0 = __half22float2(*reinterpret_cast<const __half2*>(&u0.y));
            acc[0] += w0 * a0.x; acc[1] += w0 * a0.y;
            acc[2] += w0 * b0.x; acc[3] += w0 * b0.y;
        }

        idxc = idxn;
        asc  = asn;
    }

#pragma unroll
    for (int off = 16; off; off >>= 1) zl += __shfl_xor_sync(FULLMASK, zl, off);

    float inv = 1.f / zl;
#pragma unroll
    for (int v = 0; v < 4; v++) {
        float r = acc[v] * inv + bias[lane * 4 + v];
        out[i * H1 + lane * 4 + v] = r > 0.f ? r : 0.f;
    }
}

// ---------------- agg layer 2 (H=64) FUSED with projection ------------------
// 256 threads = 8 warps = 8 nodes/block; 1250 blocks cover exactly 10000 nodes
// (no early return, so the late __syncthreads below is safe).
__global__ void __launch_bounds__(256) gat_agg2_proj_kernel(
        const float* __restrict__ bias, const float* __restrict__ Wp,
        const float* __restrict__ bp, float* __restrict__ outp) {
    __shared__ __align__(16) float Wps[H2 * EMB];   // 16 KB
    __shared__ __align__(16) float x2s[8][64];      // 2 KB (per-warp x2 rows)
    const int tid = threadIdx.x;

    // issue Wp staging loads now; sync deferred until the projection epilogue
#pragma unroll
    for (int u = 0; u < 4; u++) {
        int idx = tid + u * 256;
        *(float4*)&Wps[idx * 4] = *(const float4*)&Wp[idx * 4];
    }

    int i = (blockIdx.x * blockDim.x + tid) >> 5;   // always < N_NODES (exact grid)
    int lane = tid & 31;
    int w = tid >> 5;

    const __half* hb = g_h2h;
    float adi = g_ad[i];
    int deg = g_cnt[i];
    if (lane == 0) g_cnt[i] = 0;          // reset for next launch (last reader)
    if (deg > CAP) deg = CAP;
    const int* row = &g_csr[i * CAP];

    float es = __expf(leaky(g_as[i] + adi));
    float zl = (lane == 0) ? es : 0.f;
    float acc0, acc1;
    {
        float2 f = __half22float2(*(const __half2*)&hb[i * H2 + lane * 2]);
        acc0 = es * f.x; acc1 = es * f.y;
    }

    // prefetch chunk 0 weight chain
    int   idxc = 0;
    if (lane < deg) idxc = __ldg(&row[lane]);
    float asc = __ldg(&g_as[idxc]);

    for (int base = 0; base < deg; base += 32) {
        int rem = deg - base;
        if (rem > 32) rem = 32;

        float e = (lane < rem) ? __expf(leaky(asc + adi)) : 0.f;
        zl += e;

        int   idxn = 0;
        float asn  = 0.f;
        int nbase = base + 32;
        if (nbase < deg) {
            if (lane < deg - nbase) idxn = __ldg(&row[nbase + lane]);
            asn = __ldg(&g_as[idxn]);
        }

        int k = 0;
        for (; k + 4 <= rem; k += 4) {
            int   s0 = __shfl_sync(FULLMASK, idxc, k);
            int   s1 = __shfl_sync(FULLMASK, idxc, k + 1);
            int   s2 = __shfl_sync(FULLMASK, idxc, k + 2);
            int   s3 = __shfl_sync(FULLMASK, idxc, k + 3);
            float w0 = __shfl_sync(FULLMASK, e, k);
            float w1 = __shfl_sync(FULLMASK, e, k + 1);
            float w2 = __shfl_sync(FULLMASK, e, k + 2);
            float w3 = __shfl_sync(FULLMASK, e, k + 3);
            float2 f0 = __half22float2(*(const __half2*)&hb[s0 * H2 + lane * 2]);
            float2 f1 = __half22float2(*(const __half2*)&hb[s1 * H2 + lane * 2]);
            float2 f2 = __half22float2(*(const __half2*)&hb[s2 * H2 + lane * 2]);
            float2 f3 = __half22float2(*(const __half2*)&hb[s3 * H2 + lane * 2]);
            acc0 += w0 * f0.x + w1 * f1.x + w2 * f2.x + w3 * f3.x;
            acc1 += w0 * f0.y + w1 * f1.y + w2 * f2.y + w3 * f3.y;
        }
        for (; k < rem; ++k) {
            int   s0 = __shfl_sync(FULLMASK, idxc, k);
            float w0 = __shfl_sync(FULLMASK, e, k);
            float2 f0 = __half22float2(*(const __half2*)&hb[s0 * H2 + lane * 2]);
            acc0 += w0 * f0.x; acc1 += w0 * f0.y;
        }

        idxc = idxn;
        asc  = asn;
    }

#pragma unroll
    for (int off = 16; off; off >>= 1) zl += __shfl_xor_sync(FULLMASK, zl, off);

    float inv = 1.f / zl;
    float v0 = acc0 * inv + bias[lane * 2];
    float v1 = acc1 * inv + bias[lane * 2 + 1];
    v0 = v0 > 0.f ? v0 : 0.f;
    v1 = v1 > 0.f ? v1 : 0.f;

    // stage x2 row in smem (warp-private)
    *(float2*)&x2s[w][lane * 2] = make_float2(v0, v1);
    __syncthreads();   // joins Wp staging (issued at kernel start) + x2 rows

    float2 ob = *(const float2*)&bp[lane * 2];
    float oa0 = ob.x, oa1 = ob.y;         // chains A (even k-groups)
    float ob0 = 0.f, ob1 = 0.f;           // chains B (odd k-groups)
#pragma unroll
    for (int j = 0; j < 16; j++) {
        float4 xv = *(const float4*)&x2s[w][j * 4];   // broadcast LDS.128
        float2 w0 = *(const float2*)&Wps[(4 * j + 0) * EMB + lane * 2];
        float2 w1 = *(const float2*)&Wps[(4 * j + 1) * EMB + lane * 2];
        float2 w2 = *(const float2*)&Wps[(4 * j + 2) * EMB + lane * 2];
        float2 w3 = *(const float2*)&Wps[(4 * j + 3) * EMB + lane * 2];
        oa0 += xv.x * w0.x + xv.z * w2.x;
        oa1 += xv.x * w0.y + xv.z * w2.y;
        ob0 += xv.y * w1.x + xv.w * w3.x;
        ob1 += xv.y * w1.y + xv.w * w3.y;
    }
    *(float2*)&outp[i * EMB + lane * 2] = make_float2(oa0 + ob0, oa1 + ob1);
}

// ---------------- launch -----------------------------------------------------
extern "C" void kernel_launch(void* const* d_in, const int* in_sizes, int n_in,
                              void* d_out, int out_size) {
    const float* x    = (const float*)d_in[0];
    const int*   ei   = (const int*)d_in[1];       // int32 edge_index [2, E]
    const float* W1   = (const float*)d_in[2];
    const float* a_s1 = (const float*)d_in[3];
    const float* a_d1 = (const float*)d_in[4];
    const float* b1   = (const float*)d_in[5];
    const float* W2   = (const float*)d_in[6];
    const float* a_s2 = (const float*)d_in[7];
    const float* a_d2 = (const float*)d_in[8];
    const float* b2   = (const float*)d_in[9];
    const float* Wp   = (const float*)d_in[10];
    const float* bp   = (const float*)d_in[11];
    const int E = in_sizes[1] / 2;

    const int TB = 256;
    const int gemmBlocks = (N_NODES + 31) / 32;            // 313
    const int fillBlocks = (E + TB * 2 - 1) / (TB * 2);    // 1250 @ E=640k
    const int agg1Blocks = (N_NODES * 32 + 127) / 128;     // block=128
    const int agg2Blocks = (N_NODES * 32 + TB - 1) / TB;   // block=256, exact

    // fused: gemm1 (h1 + dots) || CSR fill — independent work, one launch
    fused_fill_gemm1_kernel<<<gemmBlocks + fillBlocks, TB>>>(
        ei, E, x, W1, a_s1, a_d1, gemmBlocks);

    // layer-1 aggregation: x1 = relu(softmax-agg(h1) + b1)
    gat_agg1_kernel<<<agg1Blocks, 128>>>(b1);

    // layer-2 GEMM: h2(fp16) = x1 @ W2 (+direct dots)
    gemm2_kernel<<<gemmBlocks, TB>>>(W2, a_s2, a_d2);

    // layer-2 aggregation fused with projection: d_out = relu(agg(h2)+b2) @ Wp + bp
    gat_agg2_proj_kernel<<<agg2Blocks, TB>>>(b2, Wp, bp, (float*)d_out);
}